// round 2
// baseline (speedup 1.0000x reference)
#include <cuda_runtime.h>
#include <math.h>

#define BATCH 8
#define CH    512
#define HGT   56
#define WID   56
#define HW    3136
#define NH    16
#define HD    32
#define TOK   25088
#define NKEY  49

// ---- scratch (device globals: no allocation allowed) ----
__device__ float g_q[(long)BATCH * NH * HW * HD];   // [b][h][i][j][d], pre-scaled
__device__ float g_k[(long)BATCH * NH * HW * HD];
__device__ float g_v[(long)BATCH * NH * HW * HD];
__device__ float g_ao[(long)TOK * CH];              // [b][i][j][c] token-major

// =====================================================================
// Kernel 1: QKV GEMM.  C[m, n] = sum_k A[m,k] * W[n,k]
// A[m,k] = x[b, k, p] with b = m/HW, p = m%HW  (coalesced along m for fixed k)
// Epilogue scatters into g_q (scaled), g_k, g_v in [b][h][pix][d] layout.
// K-tile = 16 (two 16x128 smem tiles), 32 barriers total.
// =====================================================================
__global__ __launch_bounds__(256) void qkv_gemm(const float* __restrict__ x,
                                                const float* __restrict__ w) {
    __shared__ float As[16][128];
    __shared__ float Bs[16][128];
    const int tid = threadIdx.x;
    const int tx = tid & 15, ty = tid >> 4;
    const int n0 = blockIdx.x * 128;
    const int m0 = blockIdx.y * 128;

    float acc[8][8];
#pragma unroll
    for (int i = 0; i < 8; ++i)
#pragma unroll
        for (int j = 0; j < 8; ++j) acc[i][j] = 0.f;

    // A-load: 256 threads cover 128 m x 16 k; thread handles (a_m, a_k0 + 2r), r=0..7
    const int a_m  = tid & 127;
    const int a_k0 = tid >> 7;               // 0 or 1
    const int gm   = m0 + a_m;
    const int ab   = gm / HW;
    const int ap   = gm - ab * HW;
    const float* aptr = x + (long)ab * CH * HW + ap;

    // B-load: two float4 along k per thread (covers 128 n x 16 k)
    const int b_n = tid >> 1;
    const int b_k = (tid & 1) * 8;
    const float* bptr = w + (long)(n0 + b_n) * CH + b_k;

    for (int k0 = 0; k0 < CH; k0 += 16) {
#pragma unroll
        for (int r = 0; r < 8; ++r) {
            const int kk = a_k0 + r * 2;
            As[kk][a_m] = aptr[(k0 + kk) * HW];
        }
        const float4 bv0 = *(const float4*)(bptr + k0);
        const float4 bv1 = *(const float4*)(bptr + k0 + 4);
        Bs[b_k + 0][b_n] = bv0.x;
        Bs[b_k + 1][b_n] = bv0.y;
        Bs[b_k + 2][b_n] = bv0.z;
        Bs[b_k + 3][b_n] = bv0.w;
        Bs[b_k + 4][b_n] = bv1.x;
        Bs[b_k + 5][b_n] = bv1.y;
        Bs[b_k + 6][b_n] = bv1.z;
        Bs[b_k + 7][b_n] = bv1.w;
        __syncthreads();
#pragma unroll
        for (int kk = 0; kk < 16; ++kk) {
            float a[8], bb[8];
            *(float4*)&a[0]  = *(const float4*)&As[kk][ty * 4];
            *(float4*)&a[4]  = *(const float4*)&As[kk][64 + ty * 4];
            *(float4*)&bb[0] = *(const float4*)&Bs[kk][tx * 4];
            *(float4*)&bb[4] = *(const float4*)&Bs[kk][64 + tx * 4];
#pragma unroll
            for (int i = 0; i < 8; ++i)
#pragma unroll
                for (int j = 0; j < 8; ++j) acc[i][j] += a[i] * bb[j];
        }
        __syncthreads();
    }

    const int which = n0 >> 9;                 // 0=q, 1=k, 2=v (128-tiles align with 512 splits)
    float* outp = (which == 0) ? g_q : (which == 1) ? g_k : g_v;
    const float scale = (which == 0) ? 0.17677669529663687f : 1.0f;  // 1/sqrt(32)
#pragma unroll
    for (int i = 0; i < 8; ++i) {
        const int ml  = (i < 4) ? (ty * 4 + i) : (64 + ty * 4 + (i - 4));
        const int gmi = m0 + ml;
        const int ob  = gmi / HW;
        const int op  = gmi - ob * HW;
#pragma unroll
        for (int j = 0; j < 8; ++j) {
            const int nl = (j < 4) ? (tx * 4 + j) : (64 + tx * 4 + (j - 4));
            const int n  = n0 + nl - which * 512;     // 0..511
            const int head = n >> 5, d = n & 31;
            outp[(((long)ob * NH + head) * HW + op) * HD + d] = acc[i][j] * scale;
        }
    }
}

// =====================================================================
// Kernel 2: neighborhood attention.
// CTA = (b, head, 8x4 query tile). Halo 14x10 rows of K,V (32 floats each)
// staged in static smem. Warp per query: lane = d-index, shfl-butterfly dots,
// softmax over 49 via smem logits.
// =====================================================================
#define TI 8
#define TJ 4
#define HALO_I 14
#define HALO_J 10
#define HROWS (HALO_I * HALO_J)   // 140

__global__ __launch_bounds__(128) void na_attn(const float* __restrict__ rpb) {
    __shared__ float Ks[HROWS * HD];    // 4480 floats
    __shared__ float Vs[HROWS * HD];
    __shared__ float rpbs[169];
    __shared__ float Ls[4][64];

    const int tid  = threadIdx.x;
    const int lane = tid & 31;
    const int warp = tid >> 5;
    const int tile = blockIdx.x;        // 0..97
    const int head = blockIdx.y;
    const int b    = blockIdx.z;
    const int ti = tile / (WID / TJ);   // 0..6
    const int tj = tile - ti * (WID / TJ);
    const int i0 = ti * TI;
    const int j0 = tj * TJ;
    const int base_i = max(i0 - 3, 0);
    const int base_j = max(j0 - 3, 0);
    const int bh = b * NH + head;

    // stage K/V halo (float4 granularity)
    const float4* kg = (const float4*)(g_k + (long)bh * HW * HD);
    const float4* vg = (const float4*)(g_v + (long)bh * HW * HD);
    float4* Ks4 = (float4*)Ks;
    float4* Vs4 = (float4*)Vs;
    for (int idx = tid; idx < HROWS * 8; idx += 128) {
        const int row = idx >> 3, wq = idx & 7;
        const int ry = row / HALO_J, rx = row - ry * HALO_J;
        const int gi = min(base_i + ry, HGT - 1);
        const int gj = min(base_j + rx, WID - 1);
        const int gofs = (gi * WID + gj) * 8 + wq;
        Ks4[idx] = kg[gofs];
        Vs4[idx] = vg[gofs];
    }
    for (int idx = tid; idx < 169; idx += 128) rpbs[idx] = rpb[head * 169 + idx];
    __syncthreads();

    const unsigned FULL = 0xffffffffu;
    float* Lw = Ls[warp];

    for (int q = 0; q < TI * TJ / 4; ++q) {          // 8 queries per warp
        const int qi = warp * (TI * TJ / 4) + q;     // 0..31
        const int qy = qi >> 2, qx = qi & 3;
        const int i = i0 + qy, j = j0 + qx;
        const int si = min(max(i - 3, 0), HGT - 7);
        const int sj = min(max(j - 3, 0), WID - 7);
        const int oy = si - base_i, ox = sj - base_j;
        const int bri = si - i + 6;                  // rpb row base
        const int brj = sj - j + 6;

        const float qv = g_q[((long)bh * HW + i * WID + j) * HD + lane];

#pragma unroll
        for (int t = 0; t < NKEY; ++t) {
            const int a = t / 7, c = t - a * 7;
            float d = qv * Ks[((oy + a) * HALO_J + (ox + c)) * HD + lane];
            d += __shfl_xor_sync(FULL, d, 16);
            d += __shfl_xor_sync(FULL, d, 8);
            d += __shfl_xor_sync(FULL, d, 4);
            d += __shfl_xor_sync(FULL, d, 2);
            d += __shfl_xor_sync(FULL, d, 1);
            if (lane == 0) Lw[t] = d + rpbs[(bri + a) * 13 + (brj + c)];
        }
        __syncwarp();

        // softmax over 49 (lanes hold slots lane and lane+32)
        const float l0 = Lw[lane];
        const float l1 = (lane < NKEY - 32) ? Lw[32 + lane] : -INFINITY;
        float m = fmaxf(l0, l1);
        m = fmaxf(m, __shfl_xor_sync(FULL, m, 16));
        m = fmaxf(m, __shfl_xor_sync(FULL, m, 8));
        m = fmaxf(m, __shfl_xor_sync(FULL, m, 4));
        m = fmaxf(m, __shfl_xor_sync(FULL, m, 2));
        m = fmaxf(m, __shfl_xor_sync(FULL, m, 1));
        const float e0 = expf(l0 - m);
        const float e1 = (lane < NKEY - 32) ? expf(l1 - m) : 0.f;
        float s = e0 + e1;
        s += __shfl_xor_sync(FULL, s, 16);
        s += __shfl_xor_sync(FULL, s, 8);
        s += __shfl_xor_sync(FULL, s, 4);
        s += __shfl_xor_sync(FULL, s, 2);
        s += __shfl_xor_sync(FULL, s, 1);
        const float inv = 1.f / s;
        Lw[lane] = e0 * inv;
        if (lane < NKEY - 32) Lw[32 + lane] = e1 * inv;
        __syncwarp();

        float o = 0.f;
#pragma unroll
        for (int t = 0; t < NKEY; ++t) {
            const int a = t / 7, c = t - a * 7;
            o += Lw[t] * Vs[((oy + a) * HALO_J + (ox + c)) * HD + lane];
        }
        g_ao[((long)b * HW + i * WID + j) * CH + head * HD + lane] = o;
        __syncwarp();   // protect Lw against next iteration's writes
    }
}

// =====================================================================
// Kernel 3: projection GEMM + bias + transpose to (B, C, H, W).
// A = g_ao [TOK, 512] row-major. C[m,n] = sum_k A[m,k]*W[n,k] + bias[n]
// =====================================================================
__global__ __launch_bounds__(256) void proj_gemm(const float* __restrict__ w,
                                                 const float* __restrict__ bias,
                                                 float* __restrict__ out) {
    __shared__ float As[16][128];
    __shared__ float Bs[16][128];
    const int tid = threadIdx.x;
    const int tx = tid & 15, ty = tid >> 4;
    const int n0 = blockIdx.x * 128;
    const int m0 = blockIdx.y * 128;

    float acc[8][8];
#pragma unroll
    for (int i = 0; i < 8; ++i)
#pragma unroll
        for (int j = 0; j < 8; ++j) acc[i][j] = 0.f;

    const int a_m = tid >> 1;
    const int a_k = (tid & 1) * 8;
    const float* aptr = g_ao + (long)(m0 + a_m) * CH + a_k;
    const int b_n = tid >> 1;
    const int b_k = (tid & 1) * 8;
    const float* bptr = w + (long)(n0 + b_n) * CH + b_k;

    for (int k0 = 0; k0 < CH; k0 += 16) {
        const float4 av0 = *(const float4*)(aptr + k0);
        const float4 av1 = *(const float4*)(aptr + k0 + 4);
        As[a_k + 0][a_m] = av0.x;
        As[a_k + 1][a_m] = av0.y;
        As[a_k + 2][a_m] = av0.z;
        As[a_k + 3][a_m] = av0.w;
        As[a_k + 4][a_m] = av1.x;
        As[a_k + 5][a_m] = av1.y;
        As[a_k + 6][a_m] = av1.z;
        As[a_k + 7][a_m] = av1.w;
        const float4 bv0 = *(const float4*)(bptr + k0);
        const float4 bv1 = *(const float4*)(bptr + k0 + 4);
        Bs[b_k + 0][b_n] = bv0.x;
        Bs[b_k + 1][b_n] = bv0.y;
        Bs[b_k + 2][b_n] = bv0.z;
        Bs[b_k + 3][b_n] = bv0.w;
        Bs[b_k + 4][b_n] = bv1.x;
        Bs[b_k + 5][b_n] = bv1.y;
        Bs[b_k + 6][b_n] = bv1.z;
        Bs[b_k + 7][b_n] = bv1.w;
        __syncthreads();
#pragma unroll
        for (int kk = 0; kk < 16; ++kk) {
            float a[8], bb[8];
            *(float4*)&a[0]  = *(const float4*)&As[kk][ty * 4];
            *(float4*)&a[4]  = *(const float4*)&As[kk][64 + ty * 4];
            *(float4*)&bb[0] = *(const float4*)&Bs[kk][tx * 4];
            *(float4*)&bb[4] = *(const float4*)&Bs[kk][64 + tx * 4];
#pragma unroll
            for (int i = 0; i < 8; ++i)
#pragma unroll
                for (int j = 0; j < 8; ++j) acc[i][j] += a[i] * bb[j];
        }
        __syncthreads();
    }

#pragma unroll
    for (int i = 0; i < 8; ++i) {
        const int ml  = (i < 4) ? (ty * 4 + i) : (64 + ty * 4 + (i - 4));
        const int gmi = m0 + ml;
        const int ob  = gmi / HW;
        const int op  = gmi - ob * HW;
#pragma unroll
        for (int j = 0; j < 8; ++j) {
            const int nl = (j < 4) ? (tx * 4 + j) : (64 + tx * 4 + (j - 4));
            const int n  = n0 + nl;
            out[(long)ob * CH * HW + (long)n * HW + op] = acc[i][j] + bias[n];
        }
    }
}

extern "C" void kernel_launch(void* const* d_in, const int* in_sizes, int n_in,
                              void* d_out, int out_size) {
    const float* x      = (const float*)d_in[0];
    const float* qkv_w  = (const float*)d_in[1];
    const float* rpb    = (const float*)d_in[2];
    const float* proj_w = (const float*)d_in[3];
    const float* proj_b = (const float*)d_in[4];
    float* out = (float*)d_out;

    qkv_gemm<<<dim3(1536 / 128, TOK / 128), 256>>>(x, qkv_w);
    na_attn<<<dim3((HGT / TI) * (WID / TJ), NH, BATCH), 128>>>(rpb);
    proj_gemm<<<dim3(CH / 128, TOK / 128), 256>>>(proj_w, proj_b, out);
}

// round 4
// speedup vs baseline: 2.1683x; 2.1683x over previous
#include <cuda_runtime.h>
#include <cstdint>
#include <math.h>

#define BATCH 8
#define CH    512
#define HGT   56
#define WID   56
#define HW    3136
#define NH    16
#define HD    32
#define TOK   25088
#define NKEY  49

// ---- scratch (device globals: no allocation allowed) ----
__device__ float g_q [(long)BATCH * NH * HW * HD];
__device__ float g_k [(long)BATCH * NH * HW * HD];
__device__ float g_v [(long)BATCH * NH * HW * HD];
__device__ float g_ao[(long)TOK * CH];     // attention output, token-major
__device__ float g_xt[(long)TOK * CH];     // x transposed to token-major (tf32-rounded)

// =====================================================================
// helpers
// =====================================================================
__device__ __forceinline__ uint32_t smem_u32(const void* p) {
    uint32_t a;
    asm("{ .reg .u64 t; cvta.to.shared.u64 t, %1; cvt.u32.u64 %0, t; }" : "=r"(a) : "l"(p));
    return a;
}
__device__ __forceinline__ void cpasync16(uint32_t dst, const void* src) {
    asm volatile("cp.async.cg.shared.global [%0], [%1], 16;" :: "r"(dst), "l"(src));
}
#define CP_COMMIT() asm volatile("cp.async.commit_group;" ::: "memory")

__device__ __forceinline__ uint32_t to_tf32(float f) {
    uint32_t r;
    asm("cvt.rna.tf32.f32 %0, %1;" : "=r"(r) : "f"(f));
    return r;
}
__device__ __forceinline__ void mma_tf32(float* c, const uint32_t* a, const uint32_t* b) {
    asm volatile(
        "mma.sync.aligned.m16n8k8.row.col.f32.tf32.tf32.f32 "
        "{%0,%1,%2,%3}, {%4,%5,%6,%7}, {%8,%9}, {%0,%1,%2,%3};"
        : "+f"(c[0]), "+f"(c[1]), "+f"(c[2]), "+f"(c[3])
        : "r"(a[0]), "r"(a[1]), "r"(a[2]), "r"(a[3]), "r"(b[0]), "r"(b[1]));
}

// =====================================================================
// Kernel 0: transpose x (B,C,HW) -> x_t (TOK, CH), rounded to tf32
// =====================================================================
__global__ __launch_bounds__(256) void xpose(const float* __restrict__ x) {
    __shared__ float t[32][33];
    const int b  = blockIdx.z;
    const int p0 = blockIdx.x * 32;
    const int c0 = blockIdx.y * 32;
    const int tx = threadIdx.x & 31;
    const int ty = threadIdx.x >> 5;  // 0..7
    const float* src = x + ((size_t)b * CH + c0) * HW + p0;
#pragma unroll
    for (int k = 0; k < 4; ++k) t[ty + 8 * k][tx] = src[(size_t)(ty + 8 * k) * HW + tx];
    __syncthreads();
    float* dst = g_xt + ((size_t)b * HW + p0) * CH + c0;
#pragma unroll
    for (int k = 0; k < 4; ++k)
        dst[(size_t)(ty + 8 * k) * CH + tx] = __uint_as_float(to_tf32(t[tx][ty + 8 * k]));
}

// =====================================================================
// tf32 mma.sync GEMM:  C[128m x 128n] = A[m,:] @ W[n,:]^T, K = 512
// 256 threads, 8 warps of 32x64. K-tile 16, double-buffered cp.async.
// Smem layout [row][20] (pad 4): conflict-free fragment LDS, 16B aligned.
// =====================================================================
#define KT 16

struct GemmSmem { float A[2][128][20]; float B[2][128][20]; };

__device__ __forceinline__ void g_load(GemmSmem* sm, int buf,
                                       const float* __restrict__ Ap, const float* __restrict__ Bp,
                                       int m0, int n0, int k0, int tid) {
#pragma unroll
    for (int i = 0; i < 2; ++i) {           // A: 128 rows x 4 chunks
        const int idx = tid + i * 256;
        const int row = idx >> 2, ch = idx & 3;
        cpasync16(smem_u32(&sm->A[buf][row][ch * 4]),
                  Ap + (size_t)(m0 + row) * CH + k0 + ch * 4);
    }
#pragma unroll
    for (int i = 0; i < 2; ++i) {           // B: 128 rows x 4 chunks
        const int idx = tid + i * 256;
        const int row = idx >> 2, ch = idx & 3;
        cpasync16(smem_u32(&sm->B[buf][row][ch * 4]),
                  Bp + (size_t)(n0 + row) * CH + k0 + ch * 4);
    }
    CP_COMMIT();
}

__device__ __forceinline__ void g_compute(GemmSmem* sm, int buf, float acc[2][8][4],
                                          int lane, int wm, int wn) {
#pragma unroll
    for (int ks = 0; ks < 2; ++ks) {
        const int k = ks * 8 + (lane & 3);
        uint32_t a[2][4];
#pragma unroll
        for (int mt = 0; mt < 2; ++mt) {
            const int m = wm + mt * 16 + (lane >> 2);
            a[mt][0] = to_tf32(sm->A[buf][m][k]);
            a[mt][1] = to_tf32(sm->A[buf][m + 8][k]);
            a[mt][2] = to_tf32(sm->A[buf][m][k + 4]);
            a[mt][3] = to_tf32(sm->A[buf][m + 8][k + 4]);
        }
        uint32_t b[8][2];
#pragma unroll
        for (int nt = 0; nt < 8; ++nt) {
            const int n = wn + nt * 8 + (lane >> 2);
            b[nt][0] = to_tf32(sm->B[buf][n][k]);
            b[nt][1] = to_tf32(sm->B[buf][n][k + 4]);
        }
#pragma unroll
        for (int mt = 0; mt < 2; ++mt)
#pragma unroll
            for (int nt = 0; nt < 8; ++nt) mma_tf32(acc[mt][nt], a[mt], b[nt]);
    }
}

__device__ __forceinline__ void g_mainloop(GemmSmem* sm, float acc[2][8][4],
                                           const float* __restrict__ Ap, const float* __restrict__ Bp,
                                           int m0, int n0) {
    const int tid = threadIdx.x;
    const int lane = tid & 31, wid = tid >> 5;
    const int wm = (wid & 3) * 32, wn = (wid >> 2) * 64;
#pragma unroll
    for (int mt = 0; mt < 2; ++mt)
#pragma unroll
        for (int nt = 0; nt < 8; ++nt)
#pragma unroll
            for (int r = 0; r < 4; ++r) acc[mt][nt][r] = 0.f;

    g_load(sm, 0, Ap, Bp, m0, n0, 0, tid);
    const int NTILE = CH / KT;
    for (int t = 0; t < NTILE; ++t) {
        if (t + 1 < NTILE) {
            g_load(sm, (t + 1) & 1, Ap, Bp, m0, n0, (t + 1) * KT, tid);
            asm volatile("cp.async.wait_group 1;" ::: "memory");
        } else {
            asm volatile("cp.async.wait_group 0;" ::: "memory");
        }
        __syncthreads();
        g_compute(sm, t & 1, acc, lane, wm, wn);
        __syncthreads();
    }
}

// ----- QKV: C[25088 x 1536]; scatter into g_q (scaled) / g_k / g_v -----
__global__ __launch_bounds__(256) void qkv_mma(const float* __restrict__ w) {
    __shared__ GemmSmem sm;
    float acc[2][8][4];
    const int n0 = blockIdx.x * 128;
    const int m0 = blockIdx.y * 128;
    g_mainloop(&sm, acc, g_xt, w, m0, n0);

    const int lane = threadIdx.x & 31, wid = threadIdx.x >> 5;
    const int wm = (wid & 3) * 32, wn = (wid >> 2) * 64;
    const int which = n0 >> 9;
    float* outp = (which == 0) ? g_q : (which == 1) ? g_k : g_v;
    const float sc = (which == 0) ? 0.17677669529663687f : 1.0f;

#pragma unroll
    for (int mt = 0; mt < 2; ++mt) {
        const int mA = m0 + wm + mt * 16 + (lane >> 2);
        const int bA = mA / HW, pA = mA - bA * HW;
        const int mB = mA + 8;
        const int bB = mB / HW, pB = mB - bB * HW;
#pragma unroll
        for (int nt = 0; nt < 8; ++nt) {
            const int n  = n0 + wn + nt * 8 + 2 * (lane & 3);
            const int nl = n & 511;
            const int head = nl >> 5, d = nl & 31;
            float2 v0 = make_float2(acc[mt][nt][0] * sc, acc[mt][nt][1] * sc);
            float2 v1 = make_float2(acc[mt][nt][2] * sc, acc[mt][nt][3] * sc);
            *(float2*)&outp[((size_t)(bA * NH + head) * HW + pA) * HD + d] = v0;
            *(float2*)&outp[((size_t)(bB * NH + head) * HW + pB) * HD + d] = v1;
        }
    }
}

// ----- Proj: C[25088 x 512] + bias, transposed store to (B,C,HW) -----
__global__ __launch_bounds__(256) void proj_mma(const float* __restrict__ w,
                                                const float* __restrict__ bias,
                                                float* __restrict__ out) {
    __shared__ GemmSmem sm;
    float acc[2][8][4];
    const int n0 = blockIdx.x * 128;
    const int m0 = blockIdx.y * 128;
    g_mainloop(&sm, acc, g_ao, w, m0, n0);

    const int lane = threadIdx.x & 31, wid = threadIdx.x >> 5;
    const int wm = (wid & 3) * 32, wn = (wid >> 2) * 64;

#pragma unroll
    for (int mt = 0; mt < 2; ++mt) {
        const int mA = m0 + wm + mt * 16 + (lane >> 2);
        const int bA = mA / HW, pA = mA - bA * HW;
        const int mB = mA + 8;
        const int bB = mB / HW, pB = mB - bB * HW;
#pragma unroll
        for (int nt = 0; nt < 8; ++nt) {
            const int n = n0 + wn + nt * 8 + 2 * (lane & 3);
            const float b0 = __ldg(&bias[n]), b1 = __ldg(&bias[n + 1]);
            out[((size_t)bA * CH + n) * HW + pA]     = acc[mt][nt][0] + b0;
            out[((size_t)bA * CH + n + 1) * HW + pA] = acc[mt][nt][1] + b1;
            out[((size_t)bB * CH + n) * HW + pB]     = acc[mt][nt][2] + b0;
            out[((size_t)bB * CH + n + 1) * HW + pB] = acc[mt][nt][3] + b1;
        }
    }
}

// =====================================================================
// Neighborhood attention. CTA = (b, head, 8x4 query tile).
// K/V halo rows padded to 36 floats (16B aligned, near conflict-free).
// QK: 4 keys x 8 lanes per round (LDS.128 + 4 FFMA + 3 shfl).
// AV: lane = d, probs broadcast from smem.
// =====================================================================
#define TI 8
#define TJ 4
#define HALO_I 14
#define HALO_J 10
#define HROWS (HALO_I * HALO_J)
#define KPAD 36

__global__ __launch_bounds__(128) void na_attn(const float* __restrict__ rpb) {
    __shared__ float Ks[HROWS * KPAD];
    __shared__ float Vs[HROWS * KPAD];
    __shared__ float rpbs[169];
    __shared__ float Ls[4][64];

    const int tid  = threadIdx.x;
    const int lane = tid & 31;
    const int warp = tid >> 5;
    const int tile = blockIdx.x;
    const int head = blockIdx.y;
    const int b    = blockIdx.z;
    const int ti = tile / (WID / TJ);
    const int tj = tile - ti * (WID / TJ);
    const int i0 = ti * TI;
    const int j0 = tj * TJ;
    const int base_i = max(i0 - 3, 0);
    const int base_j = max(j0 - 3, 0);
    const int bh = b * NH + head;

    // stage K/V halo (float4 granularity; rows of 32 data floats, stride 36)
    const float4* kg = (const float4*)(g_k + (size_t)bh * HW * HD);
    const float4* vg = (const float4*)(g_v + (size_t)bh * HW * HD);
    float4* Ks4 = (float4*)Ks;
    float4* Vs4 = (float4*)Vs;
    for (int idx = tid; idx < HROWS * 8; idx += 128) {
        const int row = idx >> 3, wq = idx & 7;
        const int ry = row / HALO_J, rx = row - ry * HALO_J;
        const int gi = min(base_i + ry, HGT - 1);
        const int gj = min(base_j + rx, WID - 1);
        const int gofs = (gi * WID + gj) * 8 + wq;
        Ks4[row * (KPAD / 4) + wq] = kg[gofs];
        Vs4[row * (KPAD / 4) + wq] = vg[gofs];
    }
    for (int idx = tid; idx < 169; idx += 128) rpbs[idx] = rpb[head * 169 + idx];
    __syncthreads();

    const unsigned FULL = 0xffffffffu;
    float* Lw = Ls[warp];
    const int grp  = lane >> 3;       // key sub-index within round
    const int dchk = (lane & 7) * 4;  // d-chunk base

    for (int q = 0; q < 8; ++q) {
        const int qi = warp * 8 + q;
        const int qy = qi >> 2, qx = qi & 3;
        const int i = i0 + qy, j = j0 + qx;
        const int si = min(max(i - 3, 0), HGT - 7);
        const int sj = min(max(j - 3, 0), WID - 7);
        const int oy = si - base_i, ox = sj - base_j;
        const int bri = si - i + 6;
        const int brj = sj - j + 6;
        const int rbase = oy * HALO_J + ox;

        // each lane holds the d-chunk of q for its group (broadcast load)
        const float4 q4 = *(const float4*)(g_q + ((size_t)bh * HW + i * WID + j) * HD + dchk);

        // ---- QK: rounds of 4 keys ----
#pragma unroll
        for (int r = 0; r < 13; ++r) {
            const int key = r * 4 + grp;
            const int kk  = min(key, NKEY - 1);
            const int a = kk / 7, c = kk - a * 7;
            const int row = rbase + a * HALO_J + c;
            const float4 kv = *(const float4*)&Ks[row * KPAD + dchk];
            float d = q4.x * kv.x + q4.y * kv.y + q4.z * kv.z + q4.w * kv.w;
            d += __shfl_xor_sync(FULL, d, 1);
            d += __shfl_xor_sync(FULL, d, 2);
            d += __shfl_xor_sync(FULL, d, 4);
            if ((lane & 7) == 0 && key < NKEY)
                Lw[key] = d + rpbs[(bri + a) * 13 + (brj + c)];
        }
        __syncwarp();

        // ---- softmax over 49 ----
        const float l0 = Lw[lane];
        const float l1 = (lane < NKEY - 32) ? Lw[32 + lane] : -INFINITY;
        float mx = fmaxf(l0, l1);
        mx = fmaxf(mx, __shfl_xor_sync(FULL, mx, 16));
        mx = fmaxf(mx, __shfl_xor_sync(FULL, mx, 8));
        mx = fmaxf(mx, __shfl_xor_sync(FULL, mx, 4));
        mx = fmaxf(mx, __shfl_xor_sync(FULL, mx, 2));
        mx = fmaxf(mx, __shfl_xor_sync(FULL, mx, 1));
        const float e0 = __expf(l0 - mx);
        const float e1 = (lane < NKEY - 32) ? __expf(l1 - mx) : 0.f;
        float s = e0 + e1;
        s += __shfl_xor_sync(FULL, s, 16);
        s += __shfl_xor_sync(FULL, s, 8);
        s += __shfl_xor_sync(FULL, s, 4);
        s += __shfl_xor_sync(FULL, s, 2);
        s += __shfl_xor_sync(FULL, s, 1);
        const float inv = 1.f / s;
        Lw[lane] = e0 * inv;
        if (lane < NKEY - 32) Lw[32 + lane] = e1 * inv;
        __syncwarp();

        // ---- AV: lane = d ----
        float o = 0.f;
#pragma unroll
        for (int t = 0; t < NKEY; ++t) {
            const int a = t / 7, c = t - a * 7;
            o += Lw[t] * Vs[(rbase + a * HALO_J + c) * KPAD + lane];
        }
        g_ao[((size_t)b * HW + i * WID + j) * CH + head * HD + lane] = o;
        __syncwarp();
    }
}

// =====================================================================
extern "C" void kernel_launch(void* const* d_in, const int* in_sizes, int n_in,
                              void* d_out, int out_size) {
    const float* x      = (const float*)d_in[0];
    const float* qkv_w  = (const float*)d_in[1];
    const float* rpb    = (const float*)d_in[2];
    const float* proj_w = (const float*)d_in[3];
    const float* proj_b = (const float*)d_in[4];
    float* out = (float*)d_out;

    xpose<<<dim3(HW / 32, CH / 32, BATCH), 256>>>(x);
    qkv_mma<<<dim3(1536 / 128, TOK / 128), 256>>>(qkv_w);
    na_attn<<<dim3((HGT / TI) * (WID / TJ), NH, BATCH), 128>>>(rpb);
    proj_mma<<<dim3(CH / 128, TOK / 128), 256>>>(proj_w, proj_b, out);
}

// round 6
// speedup vs baseline: 2.3511x; 1.0843x over previous
#include <cuda_runtime.h>
#include <cstdint>
#include <math.h>

#define BATCH 8
#define CH    512
#define HGT   56
#define WID   56
#define HW    3136
#define NH    16
#define HD    32
#define TOK   25088
#define NKEY  49

// ---- scratch (device globals: no allocation allowed) ----
__device__ float g_q [(long)BATCH * NH * HW * HD];
__device__ float g_k [(long)BATCH * NH * HW * HD];
__device__ float g_v [(long)BATCH * NH * HW * HD];
__device__ float g_ao[(long)TOK * CH];     // attention out, token-major, k-permuted+tf32
__device__ float g_xt[(long)TOK * CH];     // x token-major, k-permuted + tf32
__device__ float g_wq[(long)1536 * CH];    // qkv_w, k-permuted + tf32
__device__ float g_wp[(long)CH * CH];      // proj_w, k-permuted + tf32

// k-permutation within each 8-group: pairs (k, k+4) become adjacent
__device__ __forceinline__ int kperm(int k) {
    return (k & ~7) | (((k & 3) << 1) | ((k >> 2) & 1));
}

// =====================================================================
// helpers
// =====================================================================
__device__ __forceinline__ uint32_t smem_u32(const void* p) {
    uint32_t a;
    asm("{ .reg .u64 t; cvta.to.shared.u64 t, %1; cvt.u32.u64 %0, t; }" : "=r"(a) : "l"(p));
    return a;
}
__device__ __forceinline__ void cpasync16(uint32_t dst, const void* src) {
    asm volatile("cp.async.cg.shared.global [%0], [%1], 16;" :: "r"(dst), "l"(src));
}
#define CP_COMMIT() asm volatile("cp.async.commit_group;" ::: "memory")

__device__ __forceinline__ uint32_t to_tf32(float f) {
    uint32_t r;
    asm("cvt.rna.tf32.f32 %0, %1;" : "=r"(r) : "f"(f));
    return r;
}
__device__ __forceinline__ void mma_tf32(float* c, const uint32_t* a, const uint32_t* b) {
    asm volatile(
        "mma.sync.aligned.m16n8k8.row.col.f32.tf32.tf32.f32 "
        "{%0,%1,%2,%3}, {%4,%5,%6,%7}, {%8,%9}, {%0,%1,%2,%3};"
        : "+f"(c[0]), "+f"(c[1]), "+f"(c[2]), "+f"(c[3])
        : "r"(a[0]), "r"(a[1]), "r"(a[2]), "r"(a[3]), "r"(b[0]), "r"(b[1]));
}

// =====================================================================
// prep: round weights to tf32 + k-permute columns
// =====================================================================
__global__ __launch_bounds__(256) void prep_w(const float* __restrict__ src,
                                              float* __restrict__ dst, int total) {
    const int i = blockIdx.x * 256 + threadIdx.x;
    if (i < total) {
        const int k = i & 511;
        const int n = i >> 9;
        dst[(n << 9) | kperm(k)] = __uint_as_float(to_tf32(src[i]));
    }
}

// =====================================================================
// Kernel 0: transpose x (B,C,HW) -> x_t (TOK, CH), tf32 + k-permuted
// =====================================================================
__global__ __launch_bounds__(256) void xpose(const float* __restrict__ x) {
    __shared__ float t[32][33];
    const int b  = blockIdx.z;
    const int p0 = blockIdx.x * 32;
    const int c0 = blockIdx.y * 32;
    const int tx = threadIdx.x & 31;
    const int ty = threadIdx.x >> 5;  // 0..7
    const float* src = x + ((size_t)b * CH + c0) * HW + p0;
#pragma unroll
    for (int k = 0; k < 4; ++k) t[ty + 8 * k][tx] = src[(size_t)(ty + 8 * k) * HW + tx];
    __syncthreads();
    float* dst = g_xt + ((size_t)b * HW + p0) * CH + c0;
    const int ptx = kperm(tx);
#pragma unroll
    for (int k = 0; k < 4; ++k)
        dst[(size_t)(ty + 8 * k) * CH + ptx] = __uint_as_float(to_tf32(t[tx][ty + 8 * k]));
}

// =====================================================================
// tf32 mma.sync GEMM: C[128m x 128n] = A @ B^T, K=512, inputs pre-tf32,
// k-permuted so each fragment pair (k, k+4) is one LDS.64.
// Smem row stride 24 floats (96B): conflict-free LDS.64, 16B cp.async OK.
// =====================================================================
#define KT 16
#define RS 24                      // row stride in floats
#define MAT_FLOATS (128 * RS)      // 3072
#define BUF_FLOATS (2 * MAT_FLOATS)
#define GEMM_SMEM_BYTES (2 * BUF_FLOATS * 4)   // 49152

__device__ __forceinline__ void g_load(float* sm, const float* __restrict__ Ap,
                                       const float* __restrict__ Bp,
                                       int m0, int n0, int k0, int tid) {
    float* As = sm;
    float* Bs = sm + MAT_FLOATS;
#pragma unroll
    for (int i = 0; i < 2; ++i) {
        const int idx = tid + i * 256;
        const int row = idx >> 2, ch = idx & 3;
        cpasync16(smem_u32(As + row * RS + ch * 4),
                  Ap + (size_t)(m0 + row) * CH + k0 + ch * 4);
    }
#pragma unroll
    for (int i = 0; i < 2; ++i) {
        const int idx = tid + i * 256;
        const int row = idx >> 2, ch = idx & 3;
        cpasync16(smem_u32(Bs + row * RS + ch * 4),
                  Bp + (size_t)(n0 + row) * CH + k0 + ch * 4);
    }
    CP_COMMIT();
}

__device__ __forceinline__ void g_compute(const float* sm, float acc[2][8][4],
                                          int lane, int wm, int wn) {
    const float* As = sm;
    const float* Bs = sm + MAT_FLOATS;
    const int q2 = 2 * (lane & 3);
    const int mrow = lane >> 2;
#pragma unroll
    for (int ks = 0; ks < 2; ++ks) {
        const int co = ks * 8 + q2;
        uint32_t a[2][4];
#pragma unroll
        for (int mt = 0; mt < 2; ++mt) {
            const int m = wm + mt * 16 + mrow;
            const float2 lo = *(const float2*)&As[m * RS + co];
            const float2 hi = *(const float2*)&As[(m + 8) * RS + co];
            a[mt][0] = __float_as_uint(lo.x);
            a[mt][1] = __float_as_uint(hi.x);
            a[mt][2] = __float_as_uint(lo.y);
            a[mt][3] = __float_as_uint(hi.y);
        }
        uint32_t b[8][2];
#pragma unroll
        for (int nt = 0; nt < 8; ++nt) {
            const float2 bv = *(const float2*)&Bs[(wn + nt * 8 + mrow) * RS + co];
            b[nt][0] = __float_as_uint(bv.x);
            b[nt][1] = __float_as_uint(bv.y);
        }
#pragma unroll
        for (int mt = 0; mt < 2; ++mt)
#pragma unroll
            for (int nt = 0; nt < 8; ++nt) mma_tf32(acc[mt][nt], a[mt], b[nt]);
    }
}

__device__ __forceinline__ void g_mainloop(float* dynsm, float acc[2][8][4],
                                           const float* __restrict__ Ap,
                                           const float* __restrict__ Bp,
                                           int m0, int n0) {
    const int tid = threadIdx.x;
    const int lane = tid & 31, wid = tid >> 5;
    const int wm = (wid & 3) * 32, wn = (wid >> 2) * 64;
#pragma unroll
    for (int mt = 0; mt < 2; ++mt)
#pragma unroll
        for (int nt = 0; nt < 8; ++nt)
#pragma unroll
            for (int r = 0; r < 4; ++r) acc[mt][nt][r] = 0.f;

    g_load(dynsm, Ap, Bp, m0, n0, 0, tid);
    const int NTILE = CH / KT;
    for (int t = 0; t < NTILE; ++t) {
        if (t + 1 < NTILE) {
            g_load(dynsm + ((t + 1) & 1) * BUF_FLOATS, Ap, Bp, m0, n0, (t + 1) * KT, tid);
            asm volatile("cp.async.wait_group 1;" ::: "memory");
        } else {
            asm volatile("cp.async.wait_group 0;" ::: "memory");
        }
        __syncthreads();
        g_compute(dynsm + (t & 1) * BUF_FLOATS, acc, lane, wm, wn);
        __syncthreads();
    }
}

// ----- QKV: C[25088 x 1536]; scatter into g_q (scaled) / g_k / g_v -----
__global__ __launch_bounds__(256) void qkv_mma(const float* __restrict__ w) {
    extern __shared__ float dynsm[];
    float acc[2][8][4];
    const int n0 = blockIdx.x * 128;
    const int m0 = blockIdx.y * 128;
    g_mainloop(dynsm, acc, g_xt, w, m0, n0);

    const int lane = threadIdx.x & 31, wid = threadIdx.x >> 5;
    const int wm = (wid & 3) * 32, wn = (wid >> 2) * 64;
    const int which = n0 >> 9;
    float* outp = (which == 0) ? g_q : (which == 1) ? g_k : g_v;
    const float sc = (which == 0) ? 0.17677669529663687f : 1.0f;

#pragma unroll
    for (int mt = 0; mt < 2; ++mt) {
        const int mA = m0 + wm + mt * 16 + (lane >> 2);
        const int bA = mA / HW, pA = mA - bA * HW;
        const int mB = mA + 8;
        const int bB = mB / HW, pB = mB - bB * HW;
#pragma unroll
        for (int nt = 0; nt < 8; ++nt) {
            const int n  = n0 + wn + nt * 8 + 2 * (lane & 3);
            const int nl = n & 511;
            const int head = nl >> 5, d = nl & 31;
            float2 v0 = make_float2(acc[mt][nt][0] * sc, acc[mt][nt][1] * sc);
            float2 v1 = make_float2(acc[mt][nt][2] * sc, acc[mt][nt][3] * sc);
            *(float2*)&outp[((size_t)(bA * NH + head) * HW + pA) * HD + d] = v0;
            *(float2*)&outp[((size_t)(bB * NH + head) * HW + pB) * HD + d] = v1;
        }
    }
}

// ----- Proj: C[25088 x 512] + bias, transposed store to (B,C,HW) -----
__global__ __launch_bounds__(256) void proj_mma(const float* __restrict__ w,
                                                const float* __restrict__ bias,
                                                float* __restrict__ out) {
    extern __shared__ float dynsm[];
    float acc[2][8][4];
    const int n0 = blockIdx.x * 128;
    const int m0 = blockIdx.y * 128;
    g_mainloop(dynsm, acc, g_ao, w, m0, n0);

    const int lane = threadIdx.x & 31, wid = threadIdx.x >> 5;
    const int wm = (wid & 3) * 32, wn = (wid >> 2) * 64;

#pragma unroll
    for (int mt = 0; mt < 2; ++mt) {
        const int mA = m0 + wm + mt * 16 + (lane >> 2);
        const int bA = mA / HW, pA = mA - bA * HW;
        const int mB = mA + 8;
        const int bB = mB / HW, pB = mB - bB * HW;
#pragma unroll
        for (int nt = 0; nt < 8; ++nt) {
            const int n = n0 + wn + nt * 8 + 2 * (lane & 3);
            const float b0 = __ldg(&bias[n]), b1 = __ldg(&bias[n + 1]);
            out[((size_t)bA * CH + n) * HW + pA]     = acc[mt][nt][0] + b0;
            out[((size_t)bA * CH + n + 1) * HW + pA] = acc[mt][nt][1] + b1;
            out[((size_t)bB * CH + n) * HW + pB]     = acc[mt][nt][2] + b0;
            out[((size_t)bB * CH + n + 1) * HW + pB] = acc[mt][nt][3] + b1;
        }
    }
}

// =====================================================================
// Neighborhood attention (epilogue now writes tf32-rounded + k-permuted)
// =====================================================================
#define TI 8
#define TJ 4
#define HALO_I 14
#define HALO_J 10
#define HROWS (HALO_I * HALO_J)
#define KPAD 36

__global__ __launch_bounds__(128) void na_attn(const float* __restrict__ rpb) {
    __shared__ float Ks[HROWS * KPAD];
    __shared__ float Vs[HROWS * KPAD];
    __shared__ float rpbs[169];
    __shared__ float Ls[4][64];

    const int tid  = threadIdx.x;
    const int lane = tid & 31;
    const int warp = tid >> 5;
    const int tile = blockIdx.x;
    const int head = blockIdx.y;
    const int b    = blockIdx.z;
    const int ti = tile / (WID / TJ);
    const int tj = tile - ti * (WID / TJ);
    const int i0 = ti * TI;
    const int j0 = tj * TJ;
    const int base_i = max(i0 - 3, 0);
    const int base_j = max(j0 - 3, 0);
    const int bh = b * NH + head;

    const float4* kg = (const float4*)(g_k + (size_t)bh * HW * HD);
    const float4* vg = (const float4*)(g_v + (size_t)bh * HW * HD);
    float4* Ks4 = (float4*)Ks;
    float4* Vs4 = (float4*)Vs;
    for (int idx = tid; idx < HROWS * 8; idx += 128) {
        const int row = idx >> 3, wq = idx & 7;
        const int ry = row / HALO_J, rx = row - ry * HALO_J;
        const int gi = min(base_i + ry, HGT - 1);
        const int gj = min(base_j + rx, WID - 1);
        const int gofs = (gi * WID + gj) * 8 + wq;
        Ks4[row * (KPAD / 4) + wq] = kg[gofs];
        Vs4[row * (KPAD / 4) + wq] = vg[gofs];
    }
    for (int idx = tid; idx < 169; idx += 128) rpbs[idx] = rpb[head * 169 + idx];
    __syncthreads();

    const unsigned FULL = 0xffffffffu;
    float* Lw = Ls[warp];
    const int grp  = lane >> 3;
    const int dchk = (lane & 7) * 4;
    const int plane = kperm(lane);   // permuted d for g_ao store

    for (int q = 0; q < 8; ++q) {
        const int qi = warp * 8 + q;
        const int qy = qi >> 2, qx = qi & 3;
        const int i = i0 + qy, j = j0 + qx;
        const int si = min(max(i - 3, 0), HGT - 7);
        const int sj = min(max(j - 3, 0), WID - 7);
        const int oy = si - base_i, ox = sj - base_j;
        const int bri = si - i + 6;
        const int brj = sj - j + 6;
        const int rbase = oy * HALO_J + ox;

        const float4 q4 = *(const float4*)(g_q + ((size_t)bh * HW + i * WID + j) * HD + dchk);

#pragma unroll
        for (int r = 0; r < 13; ++r) {
            const int key = r * 4 + grp;
            const int kk  = min(key, NKEY - 1);
            const int a = kk / 7, c = kk - a * 7;
            const int row = rbase + a * HALO_J + c;
            const float4 kv = *(const float4*)&Ks[row * KPAD + dchk];
            float d = q4.x * kv.x + q4.y * kv.y + q4.z * kv.z + q4.w * kv.w;
            d += __shfl_xor_sync(FULL, d, 1);
            d += __shfl_xor_sync(FULL, d, 2);
            d += __shfl_xor_sync(FULL, d, 4);
            if ((lane & 7) == 0 && key < NKEY)
                Lw[key] = d + rpbs[(bri + a) * 13 + (brj + c)];
        }
        __syncwarp();

        const float l0 = Lw[lane];
        const float l1 = (lane < NKEY - 32) ? Lw[32 + lane] : -INFINITY;
        float mx = fmaxf(l0, l1);
        mx = fmaxf(mx, __shfl_xor_sync(FULL, mx, 16));
        mx = fmaxf(mx, __shfl_xor_sync(FULL, mx, 8));
        mx = fmaxf(mx, __shfl_xor_sync(FULL, mx, 4));
        mx = fmaxf(mx, __shfl_xor_sync(FULL, mx, 2));
        mx = fmaxf(mx, __shfl_xor_sync(FULL, mx, 1));
        const float e0 = __expf(l0 - mx);
        const float e1 = (lane < NKEY - 32) ? __expf(l1 - mx) : 0.f;
        float s = e0 + e1;
        s += __shfl_xor_sync(FULL, s, 16);
        s += __shfl_xor_sync(FULL, s, 8);
        s += __shfl_xor_sync(FULL, s, 4);
        s += __shfl_xor_sync(FULL, s, 2);
        s += __shfl_xor_sync(FULL, s, 1);
        const float inv = 1.f / s;
        Lw[lane] = e0 * inv;
        if (lane < NKEY - 32) Lw[32 + lane] = e1 * inv;
        __syncwarp();

        float o = 0.f;
#pragma unroll
        for (int t = 0; t < NKEY; ++t) {
            const int a = t / 7, c = t - a * 7;
            o += Lw[t] * Vs[(rbase + a * HALO_J + c) * KPAD + lane];
        }
        g_ao[((size_t)b * HW + i * WID + j) * CH + head * HD + plane] =
            __uint_as_float(to_tf32(o));
        __syncwarp();
    }
}

// =====================================================================
extern "C" void kernel_launch(void* const* d_in, const int* in_sizes, int n_in,
                              void* d_out, int out_size) {
    const float* x      = (const float*)d_in[0];
    const float* qkv_w  = (const float*)d_in[1];
    const float* rpb    = (const float*)d_in[2];
    const float* proj_w = (const float*)d_in[3];
    const float* proj_b = (const float*)d_in[4];
    float* out = (float*)d_out;

    static int configured = 0;
    if (!configured) {
        cudaFuncSetAttribute(qkv_mma,  cudaFuncAttributeMaxDynamicSharedMemorySize, GEMM_SMEM_BYTES);
        cudaFuncSetAttribute(proj_mma, cudaFuncAttributeMaxDynamicSharedMemorySize, GEMM_SMEM_BYTES);
        configured = 1;
    }

    float* wq_d; cudaGetSymbolAddress((void**)&wq_d, g_wq);
    float* wp_d; cudaGetSymbolAddress((void**)&wp_d, g_wp);

    prep_w<<<(1536 * 512 + 255) / 256, 256>>>(qkv_w, wq_d, 1536 * 512);
    prep_w<<<(512 * 512 + 255) / 256, 256>>>(proj_w, wp_d, 512 * 512);
    xpose<<<dim3(HW / 32, CH / 32, BATCH), 256>>>(x);
    qkv_mma<<<dim3(1536 / 128, TOK / 128), 256, GEMM_SMEM_BYTES>>>(wq_d);
    na_attn<<<dim3((HGT / TI) * (WID / TJ), NH, BATCH), 128>>>(rpb);
    proj_mma<<<dim3(CH / 128, TOK / 128), 256, GEMM_SMEM_BYTES>>>(wp_d, proj_b, out);
}

// round 10
// speedup vs baseline: 2.4643x; 1.0481x over previous
#include <cuda_runtime.h>
#include <cstdint>
#include <math.h>

#define BATCH 8
#define CH    512
#define HGT   56
#define WID   56
#define HW    3136
#define NH    16
#define HD    32
#define TOK   25088
#define NKEY  49

// ---- scratch (device globals: no allocation allowed) ----
__device__ float g_q [(long)BATCH * NH * HW * HD];
__device__ float g_k [(long)BATCH * NH * HW * HD];
__device__ float g_v [(long)BATCH * NH * HW * HD];
__device__ float g_ao[(long)TOK * CH];     // attention out, token-major, k-permuted+tf32
__device__ float g_xt[(long)TOK * CH];     // x token-major, k-permuted + tf32
__device__ float g_wq[(long)1536 * CH];    // qkv_w, k-permuted + tf32
__device__ float g_wp[(long)CH * CH];      // proj_w, k-permuted + tf32

// k-permutation within each 8-group: pairs (k, k+4) become adjacent
__device__ __forceinline__ int kperm(int k) {
    return (k & ~7) | (((k & 3) << 1) | ((k >> 2) & 1));
}

// =====================================================================
// helpers
// =====================================================================
__device__ __forceinline__ uint32_t smem_u32(const void* p) {
    uint32_t a;
    asm("{ .reg .u64 t; cvta.to.shared.u64 t, %1; cvt.u32.u64 %0, t; }" : "=r"(a) : "l"(p));
    return a;
}
__device__ __forceinline__ void cpasync16(uint32_t dst, const void* src) {
    asm volatile("cp.async.cg.shared.global [%0], [%1], 16;" :: "r"(dst), "l"(src));
}
#define CP_COMMIT() asm volatile("cp.async.commit_group;" ::: "memory")

__device__ __forceinline__ uint32_t to_tf32(float f) {
    uint32_t r;
    asm("cvt.rna.tf32.f32 %0, %1;" : "=r"(r) : "f"(f));
    return r;
}
__device__ __forceinline__ void mma_tf32(float* c, const uint32_t* a, const uint32_t* b) {
    asm volatile(
        "mma.sync.aligned.m16n8k8.row.col.f32.tf32.tf32.f32 "
        "{%0,%1,%2,%3}, {%4,%5,%6,%7}, {%8,%9}, {%0,%1,%2,%3};"
        : "+f"(c[0]), "+f"(c[1]), "+f"(c[2]), "+f"(c[3])
        : "r"(a[0]), "r"(a[1]), "r"(a[2]), "r"(a[3]), "r"(b[0]), "r"(b[1]));
}

// =====================================================================
// prep: round weights to tf32 + k-permute columns
// =====================================================================
__global__ __launch_bounds__(256) void prep_w(const float* __restrict__ src,
                                              float* __restrict__ dst, int total) {
    const int i = blockIdx.x * 256 + threadIdx.x;
    if (i < total) {
        const int k = i & 511;
        const int n = i >> 9;
        dst[(n << 9) | kperm(k)] = __uint_as_float(to_tf32(src[i]));
    }
}

// =====================================================================
// Kernel 0: transpose x (B,C,HW) -> x_t (TOK, CH), tf32 + k-permuted
// =====================================================================
__global__ __launch_bounds__(256) void xpose(const float* __restrict__ x) {
    __shared__ float t[32][33];
    const int b  = blockIdx.z;
    const int p0 = blockIdx.x * 32;
    const int c0 = blockIdx.y * 32;
    const int tx = threadIdx.x & 31;
    const int ty = threadIdx.x >> 5;  // 0..7
    const float* src = x + ((size_t)b * CH + c0) * HW + p0;
#pragma unroll
    for (int k = 0; k < 4; ++k) t[ty + 8 * k][tx] = src[(size_t)(ty + 8 * k) * HW + tx];
    __syncthreads();
    float* dst = g_xt + ((size_t)b * HW + p0) * CH + c0;
    const int ptx = kperm(tx);
#pragma unroll
    for (int k = 0; k < 4; ++k)
        dst[(size_t)(ty + 8 * k) * CH + ptx] = __uint_as_float(to_tf32(t[tx][ty + 8 * k]));
}

// =====================================================================
// tf32 mma.sync GEMM: C[128m x 128n] = A @ B^T, K=512, inputs pre-tf32,
// k-permuted so each fragment pair (k, k+4) is one LDS.64.
// 3-stage cp.async ring, one __syncthreads per K-tile.
// =====================================================================
#define KT 16
#define RS 24                       // smem row stride (floats)
#define MAT_FLOATS (128 * RS)       // 3072
#define MAT_BYTES  (MAT_FLOATS * 4)
#define BUF_FLOATS (2 * MAT_FLOATS)
#define BUF_BYTES  (BUF_FLOATS * 4)
#define GEMM_SMEM_BYTES (3 * BUF_BYTES)   // 73728

__device__ __forceinline__ void g_compute(const float* sm, float acc[2][8][4],
                                          int lane, int wm, int wn) {
    const float* As = sm;
    const float* Bs = sm + MAT_FLOATS;
    const int q2 = 2 * (lane & 3);
    const int mrow = lane >> 2;
#pragma unroll
    for (int ks = 0; ks < 2; ++ks) {
        const int co = ks * 8 + q2;
        uint32_t a[2][4];
#pragma unroll
        for (int mt = 0; mt < 2; ++mt) {
            const int m = wm + mt * 16 + mrow;
            const float2 lo = *(const float2*)&As[m * RS + co];
            const float2 hi = *(const float2*)&As[(m + 8) * RS + co];
            a[mt][0] = __float_as_uint(lo.x);
            a[mt][1] = __float_as_uint(hi.x);
            a[mt][2] = __float_as_uint(lo.y);
            a[mt][3] = __float_as_uint(hi.y);
        }
        uint32_t b[8][2];
#pragma unroll
        for (int nt = 0; nt < 8; ++nt) {
            const float2 bv = *(const float2*)&Bs[(wn + nt * 8 + mrow) * RS + co];
            b[nt][0] = __float_as_uint(bv.x);
            b[nt][1] = __float_as_uint(bv.y);
        }
#pragma unroll
        for (int mt = 0; mt < 2; ++mt)
#pragma unroll
            for (int nt = 0; nt < 8; ++nt) mma_tf32(acc[mt][nt], a[mt], b[nt]);
    }
}

__device__ __forceinline__ void g_mainloop(float* dynsm, float acc[2][8][4],
                                           const float* __restrict__ Ap,
                                           const float* __restrict__ Bp,
                                           int m0, int n0) {
    const int tid  = threadIdx.x;
    const int lane = tid & 31, wid = tid >> 5;
    const int wm = (wid & 3) * 32, wn = (wid >> 2) * 64;
#pragma unroll
    for (int mt = 0; mt < 2; ++mt)
#pragma unroll
        for (int nt = 0; nt < 8; ++nt)
#pragma unroll
            for (int r = 0; r < 4; ++r) acc[mt][nt][r] = 0.f;

    // per-thread load geometry (hoisted)
    const int rA0 = tid >> 2,           cA0 = tid & 3;
    const int rA1 = (tid + 256) >> 2,   cA1 = tid & 3;
    const uint32_t offA0 = (uint32_t)(rA0 * RS + cA0 * 4) * 4u;
    const uint32_t offA1 = (uint32_t)(rA1 * RS + cA1 * 4) * 4u;
    const uint32_t offB0 = offA0 + MAT_BYTES;
    const uint32_t offB1 = offA1 + MAT_BYTES;
    const float* gA0 = Ap + (size_t)(m0 + rA0) * CH + cA0 * 4;
    const float* gA1 = Ap + (size_t)(m0 + rA1) * CH + cA1 * 4;
    const float* gB0 = Bp + (size_t)(n0 + rA0) * CH + cA0 * 4;
    const float* gB1 = Bp + (size_t)(n0 + rA1) * CH + cA1 * 4;

    uint32_t sb0 = smem_u32(dynsm);
    uint32_t sb1 = sb0 + BUF_BYTES;
    uint32_t sb2 = sb0 + 2 * BUF_BYTES;

#define G_LOAD(base, k0) do { \
        cpasync16((base) + offA0, gA0 + (k0)); \
        cpasync16((base) + offA1, gA1 + (k0)); \
        cpasync16((base) + offB0, gB0 + (k0)); \
        cpasync16((base) + offB1, gB1 + (k0)); \
        CP_COMMIT(); } while (0)

    G_LOAD(sb0, 0);
    G_LOAD(sb1, KT);

    const int NT = CH / KT;   // 32
    uint32_t cur = sb0, nxt = sb1, fut = sb2;
    float* dyn0 = dynsm;
    const ptrdiff_t f2i = (ptrdiff_t)(dynsm - (float*)0);  // unused; keep simple
    (void)f2i;

#pragma unroll 3
    for (int t = 0; t < NT; ++t) {
        if (t < NT - 1) asm volatile("cp.async.wait_group 1;" ::: "memory");
        else            asm volatile("cp.async.wait_group 0;" ::: "memory");
        __syncthreads();
        if (t + 2 < NT) G_LOAD(fut, (t + 2) * KT);
        const float* cbuf = (const float*)((const char*)dyn0 + (cur - sb0));
        g_compute(cbuf, acc, lane, wm, wn);
        const uint32_t tmp = cur; cur = nxt; nxt = fut; fut = tmp;
    }
#undef G_LOAD
}

// ----- QKV: C[25088 x 1536]; scatter into g_q (scaled) / g_k / g_v -----
__global__ __launch_bounds__(256) void qkv_mma(const float* __restrict__ w) {
    extern __shared__ float dynsm[];
    float acc[2][8][4];
    const int n0 = blockIdx.x * 128;
    const int m0 = blockIdx.y * 128;
    g_mainloop(dynsm, acc, g_xt, w, m0, n0);

    const int lane = threadIdx.x & 31, wid = threadIdx.x >> 5;
    const int wm = (wid & 3) * 32, wn = (wid >> 2) * 64;
    const int which = n0 >> 9;
    float* outp = (which == 0) ? g_q : (which == 1) ? g_k : g_v;
    const float sc = (which == 0) ? 0.17677669529663687f : 1.0f;

#pragma unroll
    for (int mt = 0; mt < 2; ++mt) {
        const int mA = m0 + wm + mt * 16 + (lane >> 2);
        const int bA = mA / HW, pA = mA - bA * HW;
        const int mB = mA + 8;
        const int bB = mB / HW, pB = mB - bB * HW;
#pragma unroll
        for (int nt = 0; nt < 8; ++nt) {
            const int n  = n0 + wn + nt * 8 + 2 * (lane & 3);
            const int nl = n & 511;
            const int head = nl >> 5, d = nl & 31;
            float2 v0 = make_float2(acc[mt][nt][0] * sc, acc[mt][nt][1] * sc);
            float2 v1 = make_float2(acc[mt][nt][2] * sc, acc[mt][nt][3] * sc);
            *(float2*)&outp[((size_t)(bA * NH + head) * HW + pA) * HD + d] = v0;
            *(float2*)&outp[((size_t)(bB * NH + head) * HW + pB) * HD + d] = v1;
        }
    }
}

// ----- Proj: C[25088 x 512] + bias, transposed store to (B,C,HW) -----
__global__ __launch_bounds__(256) void proj_mma(const float* __restrict__ w,
                                                const float* __restrict__ bias,
                                                float* __restrict__ out) {
    extern __shared__ float dynsm[];
    float acc[2][8][4];
    const int n0 = blockIdx.x * 128;
    const int m0 = blockIdx.y * 128;
    g_mainloop(dynsm, acc, g_ao, w, m0, n0);

    const int lane = threadIdx.x & 31, wid = threadIdx.x >> 5;
    const int wm = (wid & 3) * 32, wn = (wid >> 2) * 64;

#pragma unroll
    for (int mt = 0; mt < 2; ++mt) {
        const int mA = m0 + wm + mt * 16 + (lane >> 2);
        const int bA = mA / HW, pA = mA - bA * HW;
        const int mB = mA + 8;
        const int bB = mB / HW, pB = mB - bB * HW;
#pragma unroll
        for (int nt = 0; nt < 8; ++nt) {
            const int n = n0 + wn + nt * 8 + 2 * (lane & 3);
            const float b0 = __ldg(&bias[n]), b1 = __ldg(&bias[n + 1]);
            out[((size_t)bA * CH + n) * HW + pA]     = acc[mt][nt][0] + b0;
            out[((size_t)bA * CH + n + 1) * HW + pA] = acc[mt][nt][1] + b1;
            out[((size_t)bB * CH + n) * HW + pB]     = acc[mt][nt][2] + b0;
            out[((size_t)bB * CH + n + 1) * HW + pB] = acc[mt][nt][3] + b1;
        }
    }
}

// =====================================================================
// Neighborhood attention. QK and AV both use the 4-group x 8-lane layout.
// =====================================================================
#define TI 8
#define TJ 4
#define HALO_I 14
#define HALO_J 10
#define HROWS (HALO_I * HALO_J)
#define KPAD 36

__global__ __launch_bounds__(128) void na_attn(const float* __restrict__ rpb) {
    __shared__ float Ks[HROWS * KPAD];
    __shared__ float Vs[HROWS * KPAD];
    __shared__ float rpbs[169];
    __shared__ float Ls[4][64];

    const int tid  = threadIdx.x;
    const int lane = tid & 31;
    const int warp = tid >> 5;
    const int tile = blockIdx.x;
    const int head = blockIdx.y;
    const int b    = blockIdx.z;
    const int ti = tile / (WID / TJ);
    const int tj = tile - ti * (WID / TJ);
    const int i0 = ti * TI;
    const int j0 = tj * TJ;
    const int base_i = max(i0 - 3, 0);
    const int base_j = max(j0 - 3, 0);
    const int bh = b * NH + head;

    const float4* kg = (const float4*)(g_k + (size_t)bh * HW * HD);
    const float4* vg = (const float4*)(g_v + (size_t)bh * HW * HD);
    float4* Ks4 = (float4*)Ks;
    float4* Vs4 = (float4*)Vs;
    for (int idx = tid; idx < HROWS * 8; idx += 128) {
        const int row = idx >> 3, wq = idx & 7;
        const int ry = row / HALO_J, rx = row - ry * HALO_J;
        const int gi = min(base_i + ry, HGT - 1);
        const int gj = min(base_j + rx, WID - 1);
        const int gofs = (gi * WID + gj) * 8 + wq;
        Ks4[row * (KPAD / 4) + wq] = kg[gofs];
        Vs4[row * (KPAD / 4) + wq] = vg[gofs];
    }
    for (int idx = tid; idx < 169; idx += 128) rpbs[idx] = rpb[head * 169 + idx];
    __syncthreads();

    const unsigned FULL = 0xffffffffu;
    float* Lw = Ls[warp];
    const int grp  = lane >> 3;       // 0..3
    const int dchk = (lane & 7) * 4;  // d-chunk base

    for (int q = 0; q < 8; ++q) {
        const int qi = warp * 8 + q;
        const int qy = qi >> 2, qx = qi & 3;
        const int i = i0 + qy, j = j0 + qx;
        const int si = min(max(i - 3, 0), HGT - 7);
        const int sj = min(max(j - 3, 0), WID - 7);
        const int oy = si - base_i, ox = sj - base_j;
        const int bri = si - i + 6;
        const int brj = sj - j + 6;
        const int rbase = oy * HALO_J + ox;

        const float4 q4 = *(const float4*)(g_q + ((size_t)bh * HW + i * WID + j) * HD + dchk);

        // ---- QK: 13 rounds of 4 keys ----
#pragma unroll
        for (int r = 0; r < 13; ++r) {
            const int key = r * 4 + grp;
            const int kk  = min(key, NKEY - 1);
            const int a = kk / 7, c = kk - a * 7;
            const int row = rbase + a * HALO_J + c;
            const float4 kv = *(const float4*)&Ks[row * KPAD + dchk];
            float d = q4.x * kv.x + q4.y * kv.y + q4.z * kv.z + q4.w * kv.w;
            d += __shfl_xor_sync(FULL, d, 1);
            d += __shfl_xor_sync(FULL, d, 2);
            d += __shfl_xor_sync(FULL, d, 4);
            if ((lane & 7) == 0 && key < NKEY)
                Lw[key] = d + rpbs[(bri + a) * 13 + (brj + c)];
        }
        __syncwarp();

        // ---- softmax over 49 ----
        const float l0 = Lw[lane];
        const float l1 = (lane < NKEY - 32) ? Lw[32 + lane] : -INFINITY;
        float mx = fmaxf(l0, l1);
        mx = fmaxf(mx, __shfl_xor_sync(FULL, mx, 16));
        mx = fmaxf(mx, __shfl_xor_sync(FULL, mx, 8));
        mx = fmaxf(mx, __shfl_xor_sync(FULL, mx, 4));
        mx = fmaxf(mx, __shfl_xor_sync(FULL, mx, 2));
        mx = fmaxf(mx, __shfl_xor_sync(FULL, mx, 1));
        const float e0 = __expf(l0 - mx);
        const float e1 = (lane < NKEY - 32) ? __expf(l1 - mx) : 0.f;
        float s = e0 + e1;
        s += __shfl_xor_sync(FULL, s, 16);
        s += __shfl_xor_sync(FULL, s, 8);
        s += __shfl_xor_sync(FULL, s, 4);
        s += __shfl_xor_sync(FULL, s, 2);
        s += __shfl_xor_sync(FULL, s, 1);
        const float inv = 1.f / s;
        Lw[lane] = e0 * inv;
        if (lane < NKEY - 32) Lw[32 + lane] = e1 * inv;
        __syncwarp();

        // ---- AV: same 4-group layout; each lane accumulates 4 d's ----
        float4 o4 = make_float4(0.f, 0.f, 0.f, 0.f);
#pragma unroll
        for (int r = 0; r < 13; ++r) {
            const int key = r * 4 + grp;
            const int kk  = min(key, NKEY - 1);
            const int a = kk / 7, c = kk - a * 7;
            const float p = (key < NKEY) ? Lw[key] : 0.f;
            const float4 v4 = *(const float4*)&Vs[(rbase + a * HALO_J + c) * KPAD + dchk];
            o4.x += p * v4.x;
            o4.y += p * v4.y;
            o4.z += p * v4.z;
            o4.w += p * v4.w;
        }
        // cross-group reduce (groups differ in lane bits 3,4)
        o4.x += __shfl_xor_sync(FULL, o4.x, 8);
        o4.y += __shfl_xor_sync(FULL, o4.y, 8);
        o4.z += __shfl_xor_sync(FULL, o4.z, 8);
        o4.w += __shfl_xor_sync(FULL, o4.w, 8);
        o4.x += __shfl_xor_sync(FULL, o4.x, 16);
        o4.y += __shfl_xor_sync(FULL, o4.y, 16);
        o4.z += __shfl_xor_sync(FULL, o4.z, 16);
        o4.w += __shfl_xor_sync(FULL, o4.w, 16);

        if (grp == 0) {
            float* dst = g_ao + ((size_t)b * HW + i * WID + j) * CH + head * HD;
            const int base8 = dchk & ~7;
            const int lo = (dchk >> 2) & 1;
            dst[base8 + lo + 0] = __uint_as_float(to_tf32(o4.x));
            dst[base8 + lo + 2] = __uint_as_float(to_tf32(o4.y));
            dst[base8 + lo + 4] = __uint_as_float(to_tf32(o4.z));
            dst[base8 + lo + 6] = __uint_as_float(to_tf32(o4.w));
        }
        __syncwarp();
    }
}

// =====================================================================
extern "C" void kernel_launch(void* const* d_in, const int* in_sizes, int n_in,
                              void* d_out, int out_size) {
    const float* x      = (const float*)d_in[0];
    const float* qkv_w  = (const float*)d_in[1];
    const float* rpb    = (const float*)d_in[2];
    const float* proj_w = (const float*)d_in[3];
    const float* proj_b = (const float*)d_in[4];
    float* out = (float*)d_out;

    cudaFuncSetAttribute(qkv_mma,  cudaFuncAttributeMaxDynamicSharedMemorySize, GEMM_SMEM_BYTES);
    cudaFuncSetAttribute(proj_mma, cudaFuncAttributeMaxDynamicSharedMemorySize, GEMM_SMEM_BYTES);

    float* wq_d; cudaGetSymbolAddress((void**)&wq_d, g_wq);
    float* wp_d; cudaGetSymbolAddress((void**)&wp_d, g_wp);

    prep_w<<<(1536 * 512 + 255) / 256, 256>>>(qkv_w, wq_d, 1536 * 512);
    prep_w<<<(512 * 512 + 255) / 256, 256>>>(proj_w, wp_d, 512 * 512);
    xpose<<<dim3(HW / 32, CH / 32, BATCH), 256>>>(x);
    qkv_mma<<<dim3(1536 / 128, TOK / 128), 256, GEMM_SMEM_BYTES>>>(wq_d);
    na_attn<<<dim3((HGT / TI) * (WID / TJ), NH, BATCH), 128>>>(rpb);
    proj_mma<<<dim3(CH / 128, TOK / 128), 256, GEMM_SMEM_BYTES>>>(wp_d, proj_b, out);
}

// round 11
// speedup vs baseline: 2.9879x; 1.2125x over previous
#include <cuda_runtime.h>
#include <cstdint>
#include <math.h>

#define BATCH 8
#define CH    512
#define HGT   56
#define WID   56
#define HW    3136
#define NH    16
#define HD    32
#define TOK   25088
#define NKEY  49

__device__ float g_q [(long)BATCH * NH * HW * HD];
__device__ float g_k [(long)BATCH * NH * HW * HD];
__device__ float g_v [(long)BATCH * NH * HW * HD];
__device__ float g_ao[(long)TOK * CH];
__device__ float g_xt[(long)TOK * CH];
__device__ float g_wq[(long)1536 * CH];
__device__ float g_wp[(long)CH * CH];

__device__ __forceinline__ int kperm(int k) {
    return (k & ~7) | (((k & 3) << 1) | ((k >> 2) & 1));
}
__device__ __forceinline__ uint32_t smem_u32(const void* p) {
    uint32_t a;
    asm("{ .reg .u64 t; cvta.to.shared.u64 t, %1; cvt.u32.u64 %0, t; }" : "=r"(a) : "l"(p));
    return a;
}
__device__ __forceinline__ void cpasync16(uint32_t dst, const void* src) {
    asm volatile("cp.async.cg.shared.global [%0], [%1], 16;" :: "r"(dst), "l"(src));
}
#define CP_COMMIT() asm volatile("cp.async.commit_group;" ::: "memory")
__device__ __forceinline__ uint32_t to_tf32(float f) {
    uint32_t r;
    asm("cvt.rna.tf32.f32 %0, %1;" : "=r"(r) : "f"(f));
    return r;
}
__device__ __forceinline__ float tf32r(float f) { return __uint_as_float(to_tf32(f)); }
__device__ __forceinline__ void mma_tf32(float* c, const uint32_t* a, const uint32_t* b) {
    asm volatile(
        "mma.sync.aligned.m16n8k8.row.col.f32.tf32.tf32.f32 "
        "{%0,%1,%2,%3}, {%4,%5,%6,%7}, {%8,%9}, {%0,%1,%2,%3};"
        : "+f"(c[0]), "+f"(c[1]), "+f"(c[2]), "+f"(c[3])
        : "r"(a[0]), "r"(a[1]), "r"(a[2]), "r"(a[3]), "r"(b[0]), "r"(b[1]));
}

// =====================================================================
__global__ __launch_bounds__(256) void prep_w(const float* __restrict__ src,
                                              float* __restrict__ dst, int total) {
    const int i = blockIdx.x * 256 + threadIdx.x;
    if (i < total) {
        const int k = i & 511;
        const int n = i >> 9;
        dst[(n << 9) | kperm(k)] = tf32r(src[i]);
    }
}

__global__ __launch_bounds__(256) void xpose(const float* __restrict__ x) {
    __shared__ float t[32][33];
    const int b  = blockIdx.z;
    const int p0 = blockIdx.x * 32;
    const int c0 = blockIdx.y * 32;
    const int tx = threadIdx.x & 31;
    const int ty = threadIdx.x >> 5;
    const float* src = x + ((size_t)b * CH + c0) * HW + p0;
#pragma unroll
    for (int k = 0; k < 4; ++k) t[ty + 8 * k][tx] = src[(size_t)(ty + 8 * k) * HW + tx];
    __syncthreads();
    float* dst = g_xt + ((size_t)b * HW + p0) * CH + c0;
    const int ptx = kperm(tx);
#pragma unroll
    for (int k = 0; k < 4; ++k)
        dst[(size_t)(ty + 8 * k) * CH + ptx] = tf32r(t[tx][ty + 8 * k]);
}

// =====================================================================
// tf32 GEMM mainloop (unchanged, known-good): 128x128 tile, 3-stage ring
// =====================================================================
#define KT 16
#define RS 24
#define MAT_FLOATS (128 * RS)
#define MAT_BYTES  (MAT_FLOATS * 4)
#define BUF_FLOATS (2 * MAT_FLOATS)
#define BUF_BYTES  (BUF_FLOATS * 4)
#define GEMM_SMEM_BYTES (3 * BUF_BYTES)

__device__ __forceinline__ void g_compute(const float* sm, float acc[2][8][4],
                                          int lane, int wm, int wn) {
    const float* As = sm;
    const float* Bs = sm + MAT_FLOATS;
    const int q2 = 2 * (lane & 3);
    const int mrow = lane >> 2;
#pragma unroll
    for (int ks = 0; ks < 2; ++ks) {
        const int co = ks * 8 + q2;
        uint32_t a[2][4];
#pragma unroll
        for (int mt = 0; mt < 2; ++mt) {
            const int m = wm + mt * 16 + mrow;
            const float2 lo = *(const float2*)&As[m * RS + co];
            const float2 hi = *(const float2*)&As[(m + 8) * RS + co];
            a[mt][0] = __float_as_uint(lo.x);
            a[mt][1] = __float_as_uint(hi.x);
            a[mt][2] = __float_as_uint(lo.y);
            a[mt][3] = __float_as_uint(hi.y);
        }
        uint32_t b[8][2];
#pragma unroll
        for (int nt = 0; nt < 8; ++nt) {
            const float2 bv = *(const float2*)&Bs[(wn + nt * 8 + mrow) * RS + co];
            b[nt][0] = __float_as_uint(bv.x);
            b[nt][1] = __float_as_uint(bv.y);
        }
#pragma unroll
        for (int mt = 0; mt < 2; ++mt)
#pragma unroll
            for (int nt = 0; nt < 8; ++nt) mma_tf32(acc[mt][nt], a[mt], b[nt]);
    }
}

__device__ __forceinline__ void g_mainloop(float* dynsm, float acc[2][8][4],
                                           const float* __restrict__ Ap,
                                           const float* __restrict__ Bp,
                                           int m0, int n0) {
    const int tid  = threadIdx.x;
    const int lane = tid & 31, wid = tid >> 5;
    const int wm = (wid & 3) * 32, wn = (wid >> 2) * 64;
#pragma unroll
    for (int mt = 0; mt < 2; ++mt)
#pragma unroll
        for (int nt = 0; nt < 8; ++nt)
#pragma unroll
            for (int r = 0; r < 4; ++r) acc[mt][nt][r] = 0.f;

    const int rA0 = tid >> 2,         cA0 = tid & 3;
    const int rA1 = (tid + 256) >> 2, cA1 = tid & 3;
    const uint32_t offA0 = (uint32_t)(rA0 * RS + cA0 * 4) * 4u;
    const uint32_t offA1 = (uint32_t)(rA1 * RS + cA1 * 4) * 4u;
    const uint32_t offB0 = offA0 + MAT_BYTES;
    const uint32_t offB1 = offA1 + MAT_BYTES;
    const float* gA0 = Ap + (size_t)(m0 + rA0) * CH + cA0 * 4;
    const float* gA1 = Ap + (size_t)(m0 + rA1) * CH + cA1 * 4;
    const float* gB0 = Bp + (size_t)(n0 + rA0) * CH + cA0 * 4;
    const float* gB1 = Bp + (size_t)(n0 + rA1) * CH + cA1 * 4;

    uint32_t sb0 = smem_u32(dynsm);
    uint32_t sb1 = sb0 + BUF_BYTES;
    uint32_t sb2 = sb0 + 2 * BUF_BYTES;

#define G_LOAD(base, k0) do { \
        cpasync16((base) + offA0, gA0 + (k0)); \
        cpasync16((base) + offA1, gA1 + (k0)); \
        cpasync16((base) + offB0, gB0 + (k0)); \
        cpasync16((base) + offB1, gB1 + (k0)); \
        CP_COMMIT(); } while (0)

    G_LOAD(sb0, 0);
    G_LOAD(sb1, KT);

    const int NT = CH / KT;
    uint32_t cur = sb0, nxt = sb1, fut = sb2;
    float* dyn0 = dynsm;

#pragma unroll 3
    for (int t = 0; t < NT; ++t) {
        if (t < NT - 1) asm volatile("cp.async.wait_group 1;" ::: "memory");
        else            asm volatile("cp.async.wait_group 0;" ::: "memory");
        __syncthreads();
        if (t + 2 < NT) G_LOAD(fut, (t + 2) * KT);
        const float* cbuf = (const float*)((const char*)dyn0 + (cur - sb0));
        g_compute(cbuf, acc, lane, wm, wn);
        const uint32_t tmp = cur; cur = nxt; nxt = fut; fut = tmp;
    }
#undef G_LOAD
}

__global__ __launch_bounds__(256) void qkv_mma(const float* __restrict__ w) {
    extern __shared__ float dynsm[];
    float acc[2][8][4];
    const int n0 = blockIdx.x * 128;
    const int m0 = blockIdx.y * 128;
    g_mainloop(dynsm, acc, g_xt, w, m0, n0);

    const int lane = threadIdx.x & 31, wid = threadIdx.x >> 5;
    const int wm = (wid & 3) * 32, wn = (wid >> 2) * 64;
    const int which = n0 >> 9;
    float* outp = (which == 0) ? g_q : (which == 1) ? g_k : g_v;
    const float sc = (which == 0) ? 0.17677669529663687f : 1.0f;

#pragma unroll
    for (int mt = 0; mt < 2; ++mt) {
        const int mA = m0 + wm + mt * 16 + (lane >> 2);
        const int bA = mA / HW, pA = mA - bA * HW;
        const int mB = mA + 8;
        const int bB = mB / HW, pB = mB - bB * HW;
#pragma unroll
        for (int nt = 0; nt < 8; ++nt) {
            const int n  = n0 + wn + nt * 8 + 2 * (lane & 3);
            const int nl = n & 511;
            const int head = nl >> 5, d = nl & 31;
            float2 v0 = make_float2(tf32r(acc[mt][nt][0] * sc), tf32r(acc[mt][nt][1] * sc));
            float2 v1 = make_float2(tf32r(acc[mt][nt][2] * sc), tf32r(acc[mt][nt][3] * sc));
            *(float2*)&outp[((size_t)(bA * NH + head) * HW + pA) * HD + d] = v0;
            *(float2*)&outp[((size_t)(bB * NH + head) * HW + pB) * HD + d] = v1;
        }
    }
}

__global__ __launch_bounds__(256) void proj_mma(const float* __restrict__ w,
                                                const float* __restrict__ bias,
                                                float* __restrict__ out) {
    extern __shared__ float dynsm[];
    float acc[2][8][4];
    const int n0 = blockIdx.x * 128;
    const int m0 = blockIdx.y * 128;
    g_mainloop(dynsm, acc, g_ao, w, m0, n0);

    const int lane = threadIdx.x & 31, wid = threadIdx.x >> 5;
    const int wm = (wid & 3) * 32, wn = (wid >> 2) * 64;

#pragma unroll
    for (int mt = 0; mt < 2; ++mt) {
        const int mA = m0 + wm + mt * 16 + (lane >> 2);
        const int bA = mA / HW, pA = mA - bA * HW;
        const int mB = mA + 8;
        const int bB = mB / HW, pB = mB - bB * HW;
#pragma unroll
        for (int nt = 0; nt < 8; ++nt) {
            const int n = n0 + wn + nt * 8 + 2 * (lane & 3);
            const float b0 = __ldg(&bias[n]), b1 = __ldg(&bias[n + 1]);
            out[((size_t)bA * CH + n) * HW + pA]     = acc[mt][nt][0] + b0;
            out[((size_t)bA * CH + n + 1) * HW + pA] = acc[mt][nt][1] + b1;
            out[((size_t)bB * CH + n) * HW + pB]     = acc[mt][nt][2] + b0;
            out[((size_t)bB * CH + n + 1) * HW + pB] = acc[mt][nt][3] + b1;
        }
    }
}

// =====================================================================
// MMA neighborhood attention.
// CTA: 8x16 query tile (4 warps of 8x4), halo 14x22 rows in smem.
// Warp: logits[32q x 144t] streamed in 18 chunks of 8 keys:
//   QK mma -> bias/exp (masked) -> shfl-repack P -> D^T += V^T @ P^T.
// Normalize by sum(exp) at the end. j-tiles {0,16,32,40} (40 overlaps).
// =====================================================================
#define AHI 14
#define AHJ 22
#define AROWS (AHI * AHJ)   // 308
#define AP 36
#define ACH 18
#define ATTN_SMEM ((2 * AROWS * AP + 176 + 128 + 144) * 4)

__global__ __launch_bounds__(128) void na_attn(const float* __restrict__ rpb) {
    extern __shared__ float asmem[];
    float* Ks     = asmem;                    // 308*36
    float* Vs     = Ks + AROWS * AP;
    float* rpbs   = Vs + AROWS * AP;          // 176
    float* normsm = rpbs + 176;               // 128
    int*   tbl    = (int*)(normsm + 128);     // 144

    const unsigned FULL = 0xffffffffu;
    const int tid = threadIdx.x, lane = tid & 31, warp = tid >> 5;
    const int tile = blockIdx.x, head = blockIdx.y, b = blockIdx.z;
    const int ti = tile >> 2, jt = tile & 3;
    const int i0 = ti * 8;
    const int j0 = (jt < 3) ? jt * 16 : 40;
    const int base_i = max(i0 - 3, 0);
    const int base_j = max(j0 - 3, 0);
    const int bh = b * NH + head;

    // ---- halo staging ----
    const float4* kg = (const float4*)(g_k + (size_t)bh * HW * HD);
    const float4* vg = (const float4*)(g_v + (size_t)bh * HW * HD);
    float4* Ks4 = (float4*)Ks;
    float4* Vs4 = (float4*)Vs;
    for (int idx = tid; idx < AROWS * 8; idx += 128) {
        const int row = idx >> 3, wq = idx & 7;
        const int ry = row / AHJ, rx = row - ry * AHJ;
        const int gi = min(base_i + ry, HGT - 1);
        const int gj = min(base_j + rx, WID - 1);
        const int g = (gi * WID + gj) * 8 + wq;
        Ks4[row * (AP / 4) + wq] = kg[g];
        Vs4[row * (AP / 4) + wq] = vg[g];
    }
    for (int idx = tid; idx < 169; idx += 128) rpbs[idx] = rpb[head * 169 + idx];
    for (int t = tid; t < 144; t += 128) {
        const int ry = t / 10, rx = t - ry * 10;
        tbl[t] = ry | (rx << 8) | ((ry * 13 + rx) << 16);
    }

    // ---- warp/query geometry ----
    const int oxw = warp * 4;
    const int minsj = min(max(j0 + oxw - 3, 0), WID - 7);
    const int wcol0 = minsj - base_j;

    int ryq[4], rxq[4], CBr[4];
#pragma unroll
    for (int s = 0; s < 4; ++s) {
        const int m = (s >> 1) * 16 + (s & 1) * 8 + (lane >> 2);
        const int qy = m >> 2, qxl = m & 3;
        const int i = i0 + qy, j = j0 + oxw + qxl;
        const int si = min(max(i - 3, 0), HGT - 7);
        const int sj = min(max(j - 3, 0), WID - 7);
        ryq[s] = si - base_i;
        rxq[s] = sj - minsj;
        CBr[s] = (base_i - i + 6) * 13 + (minsj - j + 6);
    }

    // ---- Q A-frags from gmem (pre-scaled, tf32) ----
    uint32_t qa[2][4][4];
    {
        const float* qbase = g_q + (size_t)bh * HW * HD;
        const float* qrow[4];
#pragma unroll
        for (int h = 0; h < 4; ++h) {   // h = mf*2+half
            const int m = (h >> 1) * 16 + (h & 1) * 8 + (lane >> 2);
            qrow[h] = qbase + (size_t)((i0 + (m >> 2)) * WID + j0 + oxw + (m & 3)) * HD;
        }
#pragma unroll
        for (int mf = 0; mf < 2; ++mf)
#pragma unroll
            for (int kf = 0; kf < 4; ++kf) {
                const int k0 = kf * 8 + (lane & 3);
                qa[mf][kf][0] = __float_as_uint(__ldg(qrow[mf * 2] + k0));
                qa[mf][kf][1] = __float_as_uint(__ldg(qrow[mf * 2 + 1] + k0));
                qa[mf][kf][2] = __float_as_uint(__ldg(qrow[mf * 2] + k0 + 4));
                qa[mf][kf][3] = __float_as_uint(__ldg(qrow[mf * 2 + 1] + k0 + 4));
            }
    }
    __syncthreads();

    float dT[2][4][4];
#pragma unroll
    for (int mf = 0; mf < 2; ++mf)
#pragma unroll
        for (int nf = 0; nf < 4; ++nf)
#pragma unroll
            for (int r = 0; r < 4; ++r) dT[mf][nf][r] = 0.f;
    float norm[4] = {0.f, 0.f, 0.f, 0.f};

    const int srcA = (lane & ~3) | ((lane & 3) >> 1);
    const int srcB = srcA | 2;

#pragma unroll 2
    for (int ch = 0; ch < ACH; ++ch) {
        // ---- QK chunk: logits[32 x 8] ----
        float c[2][4] = {{0.f, 0.f, 0.f, 0.f}, {0.f, 0.f, 0.f, 0.f}};
        {
            const int tb = min(ch * 8 + (lane >> 2), 139);
            const int e = tbl[tb];
            const int srow = (e & 255) * AHJ + ((e >> 8) & 255) + wcol0;
            const float* kr = Ks + srow * AP;
#pragma unroll
            for (int kf = 0; kf < 4; ++kf) {
                uint32_t bb[2];
                bb[0] = __float_as_uint(kr[kf * 8 + (lane & 3)]);
                bb[1] = __float_as_uint(kr[kf * 8 + 4 + (lane & 3)]);
                mma_tf32(c[0], qa[0][kf], bb);
                mma_tf32(c[1], qa[1][kf], bb);
            }
        }
        // ---- bias + exp (masked), no max-subtract (logits are tiny) ----
        float p[2][4];
        {
            const int t0 = ch * 8 + 2 * (lane & 3);
            const int ec0 = tbl[min(t0, 139)];
            const int ec1 = tbl[min(t0 + 1, 139)];
#pragma unroll
            for (int cc = 0; cc < 2; ++cc) {
                const int e = cc ? ec1 : ec0;
                const int ry = e & 255, rx = (e >> 8) & 255, r13 = e >> 16;
                const bool tv = (t0 + cc) < 140;
#pragma unroll
                for (int s = 0; s < 4; ++s) {
                    const int mf = s >> 1, rh = s & 1;
                    const float cv = c[mf][rh * 2 + cc];
                    const bool v = tv && ((unsigned)(ry - ryq[s]) <= 6u)
                                      && ((unsigned)(rx - rxq[s]) <= 6u);
                    int bi = r13 + CBr[s];
                    bi = max(min(bi, 168), 0);
                    float ev = v ? __expf(cv + rpbs[bi]) : 0.f;
                    ev = tf32r(ev);
                    p[mf][rh * 2 + cc] = ev;
                    norm[s] += ev;
                }
            }
        }
        // ---- AV chunk: D^T += V^T @ P^T ----
        {
            const int ea = tbl[min(ch * 8 + (lane & 3), 139)];
            const int eb = tbl[min(ch * 8 + 4 + (lane & 3), 139)];
            const int ra = (ea & 255) * AHJ + ((ea >> 8) & 255) + wcol0;
            const int rb = (eb & 255) * AHJ + ((eb >> 8) & 255) + wcol0;
            const float* v0 = Vs + ra * AP;
            const float* v4 = Vs + rb * AP;
            uint32_t av[2][4];
#pragma unroll
            for (int mf = 0; mf < 2; ++mf) {
                const int d0 = mf * 16 + (lane >> 2);
                av[mf][0] = __float_as_uint(v0[d0]);
                av[mf][1] = __float_as_uint(v0[d0 + 8]);
                av[mf][2] = __float_as_uint(v4[d0]);
                av[mf][3] = __float_as_uint(v4[d0 + 8]);
            }
#pragma unroll
            for (int nf = 0; nf < 4; ++nf) {
                const float va0 = p[nf >> 1][(nf & 1) * 2];
                const float va1 = p[nf >> 1][(nf & 1) * 2 + 1];
                const float s0 = __shfl_sync(FULL, va0, srcA);
                const float s1 = __shfl_sync(FULL, va1, srcA);
                const float u0 = __shfl_sync(FULL, va0, srcB);
                const float u1 = __shfl_sync(FULL, va1, srcB);
                uint32_t bb[2];
                bb[0] = __float_as_uint((lane & 1) ? s1 : s0);
                bb[1] = __float_as_uint((lane & 1) ? u1 : u0);
                mma_tf32(dT[0][nf], av[0], bb);
                mma_tf32(dT[1][nf], av[1], bb);
            }
        }
    }

    // ---- normalize + store (g_ao token-major, kperm'd + tf32) ----
#pragma unroll
    for (int s = 0; s < 4; ++s) {
        float n = norm[s];
        n += __shfl_xor_sync(FULL, n, 1);
        n += __shfl_xor_sync(FULL, n, 2);
        if ((lane & 3) == 0)
            normsm[warp * 32 + (s >> 1) * 16 + (s & 1) * 8 + (lane >> 2)] = 1.f / n;
    }
    __syncwarp();

    const int dlo = lane >> 2;
#pragma unroll
    for (int mf = 0; mf < 2; ++mf) {
        const int d0 = mf * 16 + dlo, d1 = d0 + 8;
        const int kp0 = kperm(d0), kp1 = kperm(d1);
#pragma unroll
        for (int nf = 0; nf < 4; ++nf) {
            const int q0 = nf * 8 + 2 * (lane & 3), q1 = q0 + 1;
            const float iv0 = normsm[warp * 32 + q0];
            const float iv1 = normsm[warp * 32 + q1];
            float* p0 = g_ao + ((size_t)b * HW + (i0 + (q0 >> 2)) * WID + j0 + oxw + (q0 & 3)) * CH + head * HD;
            float* p1 = g_ao + ((size_t)b * HW + (i0 + (q1 >> 2)) * WID + j0 + oxw + (q1 & 3)) * CH + head * HD;
            p0[kp0] = tf32r(dT[mf][nf][0] * iv0);
            p1[kp0] = tf32r(dT[mf][nf][1] * iv1);
            p0[kp1] = tf32r(dT[mf][nf][2] * iv0);
            p1[kp1] = tf32r(dT[mf][nf][3] * iv1);
        }
    }
}

// =====================================================================
extern "C" void kernel_launch(void* const* d_in, const int* in_sizes, int n_in,
                              void* d_out, int out_size) {
    const float* x      = (const float*)d_in[0];
    const float* qkv_w  = (const float*)d_in[1];
    const float* rpb    = (const float*)d_in[2];
    const float* proj_w = (const float*)d_in[3];
    const float* proj_b = (const float*)d_in[4];
    float* out = (float*)d_out;

    cudaFuncSetAttribute(qkv_mma,  cudaFuncAttributeMaxDynamicSharedMemorySize, GEMM_SMEM_BYTES);
    cudaFuncSetAttribute(proj_mma, cudaFuncAttributeMaxDynamicSharedMemorySize, GEMM_SMEM_BYTES);
    cudaFuncSetAttribute(na_attn,  cudaFuncAttributeMaxDynamicSharedMemorySize, ATTN_SMEM);

    float* wq_d; cudaGetSymbolAddress((void**)&wq_d, g_wq);
    float* wp_d; cudaGetSymbolAddress((void**)&wp_d, g_wp);

    prep_w<<<(1536 * 512 + 255) / 256, 256>>>(qkv_w, wq_d, 1536 * 512);
    prep_w<<<(512 * 512 + 255) / 256, 256>>>(proj_w, wp_d, 512 * 512);
    xpose<<<dim3(HW / 32, CH / 32, BATCH), 256>>>(x);
    qkv_mma<<<dim3(1536 / 128, TOK / 128), 256, GEMM_SMEM_BYTES>>>(wq_d);
    na_attn<<<dim3(28, NH, BATCH), 128, ATTN_SMEM>>>(rpb);
    proj_mma<<<dim3(CH / 128, TOK / 128), 256, GEMM_SMEM_BYTES>>>(wp_d, proj_b, out);
}

// round 12
// speedup vs baseline: 3.0838x; 1.0321x over previous
#include <cuda_runtime.h>
#include <cstdint>
#include <math.h>

#define BATCH 8
#define CH    512
#define HGT   56
#define WID   56
#define HW    3136
#define NH    16
#define HD    32
#define TOK   25088
#define NKEY  49

__device__ float g_q [(long)BATCH * NH * HW * HD];
__device__ float g_k [(long)BATCH * NH * HW * HD];
__device__ float g_v [(long)BATCH * NH * HW * HD];
__device__ float g_ao[(long)TOK * CH];
__device__ float g_xt[(long)TOK * CH];
__device__ float g_wq[(long)1536 * CH];
__device__ float g_wp[(long)CH * CH];

__device__ __forceinline__ int kperm(int k) {
    return (k & ~7) | (((k & 3) << 1) | ((k >> 2) & 1));
}
__device__ __forceinline__ uint32_t smem_u32(const void* p) {
    uint32_t a;
    asm("{ .reg .u64 t; cvta.to.shared.u64 t, %1; cvt.u32.u64 %0, t; }" : "=r"(a) : "l"(p));
    return a;
}
__device__ __forceinline__ void cpasync16(uint32_t dst, const void* src) {
    asm volatile("cp.async.cg.shared.global [%0], [%1], 16;" :: "r"(dst), "l"(src));
}
#define CP_COMMIT() asm volatile("cp.async.commit_group;" ::: "memory")
__device__ __forceinline__ uint32_t to_tf32(float f) {
    uint32_t r;
    asm("cvt.rna.tf32.f32 %0, %1;" : "=r"(r) : "f"(f));
    return r;
}
__device__ __forceinline__ float tf32r(float f) { return __uint_as_float(to_tf32(f)); }
__device__ __forceinline__ void mma_tf32(float* c, const uint32_t* a, const uint32_t* b) {
    asm volatile(
        "mma.sync.aligned.m16n8k8.row.col.f32.tf32.tf32.f32 "
        "{%0,%1,%2,%3}, {%4,%5,%6,%7}, {%8,%9}, {%0,%1,%2,%3};"
        : "+f"(c[0]), "+f"(c[1]), "+f"(c[2]), "+f"(c[3])
        : "r"(a[0]), "r"(a[1]), "r"(a[2]), "r"(a[3]), "r"(b[0]), "r"(b[1]));
}

// =====================================================================
__global__ __launch_bounds__(256) void prep_w(const float* __restrict__ src,
                                              float* __restrict__ dst, int total) {
    const int i = blockIdx.x * 256 + threadIdx.x;
    if (i < total) {
        const int k = i & 511;
        const int n = i >> 9;
        dst[(n << 9) | kperm(k)] = tf32r(src[i]);
    }
}

__global__ __launch_bounds__(256) void xpose(const float* __restrict__ x) {
    __shared__ float t[32][33];
    const int b  = blockIdx.z;
    const int p0 = blockIdx.x * 32;
    const int c0 = blockIdx.y * 32;
    const int tx = threadIdx.x & 31;
    const int ty = threadIdx.x >> 5;
    const float* src = x + ((size_t)b * CH + c0) * HW + p0;
#pragma unroll
    for (int k = 0; k < 4; ++k) t[ty + 8 * k][tx] = src[(size_t)(ty + 8 * k) * HW + tx];
    __syncthreads();
    float* dst = g_xt + ((size_t)b * HW + p0) * CH + c0;
    const int ptx = kperm(tx);
#pragma unroll
    for (int k = 0; k < 4; ++k)
        dst[(size_t)(ty + 8 * k) * CH + ptx] = tf32r(t[tx][ty + 8 * k]);
}

// =====================================================================
// tf32 GEMM: CTA tile 128m x 256n, 512 threads (16 warps of 32x64),
// KT=32, 3-stage cp.async ring, smem row stride 40 (conflict-free).
// =====================================================================
#define KT 32
#define RS 40
#define A_FLOATS (128 * RS)          // 5120
#define A_BYTES  (A_FLOATS * 4)      // 20480
#define B_FLOATS (256 * RS)          // 10240
#define STG_FLOATS (A_FLOATS + B_FLOATS)
#define STG_BYTES  (STG_FLOATS * 4)  // 61440
#define GEMM_SMEM_BYTES (3 * STG_BYTES)  // 184320

__device__ __forceinline__ void g_compute(const float* sm, float acc[2][8][4],
                                          int lane, int wm, int wn) {
    const float* As = sm;
    const float* Bs = sm + A_FLOATS;
    const int q2 = 2 * (lane & 3);
    const int mrow = lane >> 2;
#pragma unroll
    for (int ks = 0; ks < 4; ++ks) {
        const int co = ks * 8 + q2;
        uint32_t a[2][4];
#pragma unroll
        for (int mt = 0; mt < 2; ++mt) {
            const int m = wm + mt * 16 + mrow;
            const float2 lo = *(const float2*)&As[m * RS + co];
            const float2 hi = *(const float2*)&As[(m + 8) * RS + co];
            a[mt][0] = __float_as_uint(lo.x);
            a[mt][1] = __float_as_uint(hi.x);
            a[mt][2] = __float_as_uint(lo.y);
            a[mt][3] = __float_as_uint(hi.y);
        }
        uint32_t b[8][2];
#pragma unroll
        for (int nt = 0; nt < 8; ++nt) {
            const float2 bv = *(const float2*)&Bs[(wn + nt * 8 + mrow) * RS + co];
            b[nt][0] = __float_as_uint(bv.x);
            b[nt][1] = __float_as_uint(bv.y);
        }
#pragma unroll
        for (int mt = 0; mt < 2; ++mt)
#pragma unroll
            for (int nt = 0; nt < 8; ++nt) mma_tf32(acc[mt][nt], a[mt], b[nt]);
    }
}

__device__ __forceinline__ void g_mainloop(float* dynsm, float acc[2][8][4],
                                           const float* __restrict__ Ap,
                                           const float* __restrict__ Bp,
                                           int m0, int n0) {
    const int tid  = threadIdx.x;
    const int lane = tid & 31, wid = tid >> 5;
    const int wm = (wid & 3) * 32, wn = (wid >> 2) * 64;
#pragma unroll
    for (int mt = 0; mt < 2; ++mt)
#pragma unroll
        for (int nt = 0; nt < 8; ++nt)
#pragma unroll
            for (int r = 0; r < 4; ++r) acc[mt][nt][r] = 0.f;

    // load geometry: rows of 32 floats = 8 chunks of 4; 512 threads.
    const int r0 = tid >> 3;                 // 0..63
    const int c0 = (tid & 7) * 4;            // float offset in k
    const uint32_t offA0 = (uint32_t)(r0 * RS + c0) * 4u;
    const uint32_t offA1 = (uint32_t)((r0 + 64) * RS + c0) * 4u;
    const uint32_t offB0 = (uint32_t)(r0 * RS + c0) * 4u + A_BYTES;
    const uint32_t offB1 = (uint32_t)((r0 + 64) * RS + c0) * 4u + A_BYTES;
    const uint32_t offB2 = (uint32_t)((r0 + 128) * RS + c0) * 4u + A_BYTES;
    const uint32_t offB3 = (uint32_t)((r0 + 192) * RS + c0) * 4u + A_BYTES;
    const float* gA0 = Ap + (size_t)(m0 + r0) * CH + c0;
    const float* gA1 = Ap + (size_t)(m0 + r0 + 64) * CH + c0;
    const float* gB0 = Bp + (size_t)(n0 + r0) * CH + c0;
    const float* gB1 = Bp + (size_t)(n0 + r0 + 64) * CH + c0;
    const float* gB2 = Bp + (size_t)(n0 + r0 + 128) * CH + c0;
    const float* gB3 = Bp + (size_t)(n0 + r0 + 192) * CH + c0;

    const uint32_t sb0 = smem_u32(dynsm);
    const uint32_t sb1 = sb0 + STG_BYTES;
    const uint32_t sb2 = sb0 + 2 * STG_BYTES;

#define G_LOAD(base, k0) do { \
        cpasync16((base) + offA0, gA0 + (k0)); \
        cpasync16((base) + offA1, gA1 + (k0)); \
        cpasync16((base) + offB0, gB0 + (k0)); \
        cpasync16((base) + offB1, gB1 + (k0)); \
        cpasync16((base) + offB2, gB2 + (k0)); \
        cpasync16((base) + offB3, gB3 + (k0)); \
        CP_COMMIT(); } while (0)

    G_LOAD(sb0, 0);
    G_LOAD(sb1, KT);

    const int NT = CH / KT;   // 16
    uint32_t cur = sb0, nxt = sb1, fut = sb2;
    float* dyn0 = dynsm;

#pragma unroll 3
    for (int t = 0; t < NT; ++t) {
        if (t < NT - 1) asm volatile("cp.async.wait_group 1;" ::: "memory");
        else            asm volatile("cp.async.wait_group 0;" ::: "memory");
        __syncthreads();
        if (t + 2 < NT) G_LOAD(fut, (t + 2) * KT);
        const float* cbuf = (const float*)((const char*)dyn0 + (cur - sb0));
        g_compute(cbuf, acc, lane, wm, wn);
        const uint32_t tmp = cur; cur = nxt; nxt = fut; fut = tmp;
    }
#undef G_LOAD
}

// ----- QKV: tiles of 256 n lie entirely inside one of q/k/v -----
__global__ __launch_bounds__(512) void qkv_mma(const float* __restrict__ w) {
    extern __shared__ float dynsm[];
    float acc[2][8][4];
    const int n0 = blockIdx.x * 256;
    const int m0 = blockIdx.y * 128;
    g_mainloop(dynsm, acc, g_xt, w, m0, n0);

    const int lane = threadIdx.x & 31, wid = threadIdx.x >> 5;
    const int wm = (wid & 3) * 32, wn = (wid >> 2) * 64;
    const int which = n0 >> 9;
    float* outp = (which == 0) ? g_q : (which == 1) ? g_k : g_v;
    const float sc = (which == 0) ? 0.17677669529663687f : 1.0f;

#pragma unroll
    for (int mt = 0; mt < 2; ++mt) {
        const int mA = m0 + wm + mt * 16 + (lane >> 2);
        const int bA = mA / HW, pA = mA - bA * HW;
        const int mB = mA + 8;
        const int bB = mB / HW, pB = mB - bB * HW;
#pragma unroll
        for (int nt = 0; nt < 8; ++nt) {
            const int n  = n0 + wn + nt * 8 + 2 * (lane & 3);
            const int nl = n & 511;
            const int head = nl >> 5, d = nl & 31;
            float2 v0 = make_float2(tf32r(acc[mt][nt][0] * sc), tf32r(acc[mt][nt][1] * sc));
            float2 v1 = make_float2(tf32r(acc[mt][nt][2] * sc), tf32r(acc[mt][nt][3] * sc));
            *(float2*)&outp[((size_t)(bA * NH + head) * HW + pA) * HD + d] = v0;
            *(float2*)&outp[((size_t)(bB * NH + head) * HW + pB) * HD + d] = v1;
        }
    }
}

__global__ __launch_bounds__(512) void proj_mma(const float* __restrict__ w,
                                                const float* __restrict__ bias,
                                                float* __restrict__ out) {
    extern __shared__ float dynsm[];
    float acc[2][8][4];
    const int n0 = blockIdx.x * 256;
    const int m0 = blockIdx.y * 128;
    g_mainloop(dynsm, acc, g_ao, w, m0, n0);

    const int lane = threadIdx.x & 31, wid = threadIdx.x >> 5;
    const int wm = (wid & 3) * 32, wn = (wid >> 2) * 64;

#pragma unroll
    for (int mt = 0; mt < 2; ++mt) {
        const int mA = m0 + wm + mt * 16 + (lane >> 2);
        const int bA = mA / HW, pA = mA - bA * HW;
        const int mB = mA + 8;
        const int bB = mB / HW, pB = mB - bB * HW;
#pragma unroll
        for (int nt = 0; nt < 8; ++nt) {
            const int n = n0 + wn + nt * 8 + 2 * (lane & 3);
            const float b0 = __ldg(&bias[n]), b1 = __ldg(&bias[n + 1]);
            out[((size_t)bA * CH + n) * HW + pA]     = acc[mt][nt][0] + b0;
            out[((size_t)bA * CH + n + 1) * HW + pA] = acc[mt][nt][1] + b1;
            out[((size_t)bB * CH + n) * HW + pB]     = acc[mt][nt][2] + b0;
            out[((size_t)bB * CH + n + 1) * HW + pB] = acc[mt][nt][3] + b1;
        }
    }
}

// =====================================================================
// MMA neighborhood attention (unchanged from round-11 winner)
// =====================================================================
#define AHI 14
#define AHJ 22
#define AROWS (AHI * AHJ)
#define AP 36
#define ACH 18
#define ATTN_SMEM ((2 * AROWS * AP + 176 + 128 + 144) * 4)

__global__ __launch_bounds__(128) void na_attn(const float* __restrict__ rpb) {
    extern __shared__ float asmem[];
    float* Ks     = asmem;
    float* Vs     = Ks + AROWS * AP;
    float* rpbs   = Vs + AROWS * AP;
    float* normsm = rpbs + 176;
    int*   tbl    = (int*)(normsm + 128);

    const unsigned FULL = 0xffffffffu;
    const int tid = threadIdx.x, lane = tid & 31, warp = tid >> 5;
    const int tile = blockIdx.x, head = blockIdx.y, b = blockIdx.z;
    const int ti = tile >> 2, jt = tile & 3;
    const int i0 = ti * 8;
    const int j0 = (jt < 3) ? jt * 16 : 40;
    const int base_i = max(i0 - 3, 0);
    const int base_j = max(j0 - 3, 0);
    const int bh = b * NH + head;

    const float4* kg = (const float4*)(g_k + (size_t)bh * HW * HD);
    const float4* vg = (const float4*)(g_v + (size_t)bh * HW * HD);
    float4* Ks4 = (float4*)Ks;
    float4* Vs4 = (float4*)Vs;
    for (int idx = tid; idx < AROWS * 8; idx += 128) {
        const int row = idx >> 3, wq = idx & 7;
        const int ry = row / AHJ, rx = row - ry * AHJ;
        const int gi = min(base_i + ry, HGT - 1);
        const int gj = min(base_j + rx, WID - 1);
        const int g = (gi * WID + gj) * 8 + wq;
        Ks4[row * (AP / 4) + wq] = kg[g];
        Vs4[row * (AP / 4) + wq] = vg[g];
    }
    for (int idx = tid; idx < 169; idx += 128) rpbs[idx] = rpb[head * 169 + idx];
    for (int t = tid; t < 144; t += 128) {
        const int ry = t / 10, rx = t - ry * 10;
        tbl[t] = ry | (rx << 8) | ((ry * 13 + rx) << 16);
    }

    const int oxw = warp * 4;
    const int minsj = min(max(j0 + oxw - 3, 0), WID - 7);
    const int wcol0 = minsj - base_j;

    int ryq[4], rxq[4], CBr[4];
#pragma unroll
    for (int s = 0; s < 4; ++s) {
        const int m = (s >> 1) * 16 + (s & 1) * 8 + (lane >> 2);
        const int qy = m >> 2, qxl = m & 3;
        const int i = i0 + qy, j = j0 + oxw + qxl;
        const int si = min(max(i - 3, 0), HGT - 7);
        const int sj = min(max(j - 3, 0), WID - 7);
        ryq[s] = si - base_i;
        rxq[s] = sj - minsj;
        CBr[s] = (base_i - i + 6) * 13 + (minsj - j + 6);
    }

    uint32_t qa[2][4][4];
    {
        const float* qbase = g_q + (size_t)bh * HW * HD;
        const float* qrow[4];
#pragma unroll
        for (int h = 0; h < 4; ++h) {
            const int m = (h >> 1) * 16 + (h & 1) * 8 + (lane >> 2);
            qrow[h] = qbase + (size_t)((i0 + (m >> 2)) * WID + j0 + oxw + (m & 3)) * HD;
        }
#pragma unroll
        for (int mf = 0; mf < 2; ++mf)
#pragma unroll
            for (int kf = 0; kf < 4; ++kf) {
                const int k0 = kf * 8 + (lane & 3);
                qa[mf][kf][0] = __float_as_uint(__ldg(qrow[mf * 2] + k0));
                qa[mf][kf][1] = __float_as_uint(__ldg(qrow[mf * 2 + 1] + k0));
                qa[mf][kf][2] = __float_as_uint(__ldg(qrow[mf * 2] + k0 + 4));
                qa[mf][kf][3] = __float_as_uint(__ldg(qrow[mf * 2 + 1] + k0 + 4));
            }
    }
    __syncthreads();

    float dT[2][4][4];
#pragma unroll
    for (int mf = 0; mf < 2; ++mf)
#pragma unroll
        for (int nf = 0; nf < 4; ++nf)
#pragma unroll
            for (int r = 0; r < 4; ++r) dT[mf][nf][r] = 0.f;
    float norm[4] = {0.f, 0.f, 0.f, 0.f};

    const int srcA = (lane & ~3) | ((lane & 3) >> 1);
    const int srcB = srcA | 2;

#pragma unroll 2
    for (int ch = 0; ch < ACH; ++ch) {
        float c[2][4] = {{0.f, 0.f, 0.f, 0.f}, {0.f, 0.f, 0.f, 0.f}};
        {
            const int tb = min(ch * 8 + (lane >> 2), 139);
            const int e = tbl[tb];
            const int srow = (e & 255) * AHJ + ((e >> 8) & 255) + wcol0;
            const float* kr = Ks + srow * AP;
#pragma unroll
            for (int kf = 0; kf < 4; ++kf) {
                uint32_t bb[2];
                bb[0] = __float_as_uint(kr[kf * 8 + (lane & 3)]);
                bb[1] = __float_as_uint(kr[kf * 8 + 4 + (lane & 3)]);
                mma_tf32(c[0], qa[0][kf], bb);
                mma_tf32(c[1], qa[1][kf], bb);
            }
        }
        float p[2][4];
        {
            const int t0 = ch * 8 + 2 * (lane & 3);
            const int ec0 = tbl[min(t0, 139)];
            const int ec1 = tbl[min(t0 + 1, 139)];
#pragma unroll
            for (int cc = 0; cc < 2; ++cc) {
                const int e = cc ? ec1 : ec0;
                const int ry = e & 255, rx = (e >> 8) & 255, r13 = e >> 16;
                const bool tv = (t0 + cc) < 140;
#pragma unroll
                for (int s = 0; s < 4; ++s) {
                    const int mf = s >> 1, rh = s & 1;
                    const float cv = c[mf][rh * 2 + cc];
                    const bool v = tv && ((unsigned)(ry - ryq[s]) <= 6u)
                                      && ((unsigned)(rx - rxq[s]) <= 6u);
                    int bi = r13 + CBr[s];
                    bi = max(min(bi, 168), 0);
                    float ev = v ? __expf(cv + rpbs[bi]) : 0.f;
                    ev = tf32r(ev);
                    p[mf][rh * 2 + cc] = ev;
                    norm[s] += ev;
                }
            }
        }
        {
            const int ea = tbl[min(ch * 8 + (lane & 3), 139)];
            const int eb = tbl[min(ch * 8 + 4 + (lane & 3), 139)];
            const int ra = (ea & 255) * AHJ + ((ea >> 8) & 255) + wcol0;
            const int rb = (eb & 255) * AHJ + ((eb >> 8) & 255) + wcol0;
            const float* v0 = Vs + ra * AP;
            const float* v4 = Vs + rb * AP;
            uint32_t av[2][4];
#pragma unroll
            for (int mf = 0; mf < 2; ++mf) {
                const int d0 = mf * 16 + (lane >> 2);
                av[mf][0] = __float_as_uint(v0[d0]);
                av[mf][1] = __float_as_uint(v0[d0 + 8]);
                av[mf][2] = __float_as_uint(v4[d0]);
                av[mf][3] = __float_as_uint(v4[d0 + 8]);
            }
#pragma unroll
            for (int nf = 0; nf < 4; ++nf) {
                const float va0 = p[nf >> 1][(nf & 1) * 2];
                const float va1 = p[nf >> 1][(nf & 1) * 2 + 1];
                const float s0 = __shfl_sync(FULL, va0, srcA);
                const float s1 = __shfl_sync(FULL, va1, srcA);
                const float u0 = __shfl_sync(FULL, va0, srcB);
                const float u1 = __shfl_sync(FULL, va1, srcB);
                uint32_t bb[2];
                bb[0] = __float_as_uint((lane & 1) ? s1 : s0);
                bb[1] = __float_as_uint((lane & 1) ? u1 : u0);
                mma_tf32(dT[0][nf], av[0], bb);
                mma_tf32(dT[1][nf], av[1], bb);
            }
        }
    }

#pragma unroll
    for (int s = 0; s < 4; ++s) {
        float n = norm[s];
        n += __shfl_xor_sync(FULL, n, 1);
        n += __shfl_xor_sync(FULL, n, 2);
        if ((lane & 3) == 0)
            normsm[warp * 32 + (s >> 1) * 16 + (s & 1) * 8 + (lane >> 2)] = 1.f / n;
    }
    __syncwarp();

    const int dlo = lane >> 2;
#pragma unroll
    for (int mf = 0; mf < 2; ++mf) {
        const int d0 = mf * 16 + dlo, d1 = d0 + 8;
        const int kp0 = kperm(d0), kp1 = kperm(d1);
#pragma unroll
        for (int nf = 0; nf < 4; ++nf) {
            const int q0 = nf * 8 + 2 * (lane & 3), q1 = q0 + 1;
            const float iv0 = normsm[warp * 32 + q0];
            const float iv1 = normsm[warp * 32 + q1];
            float* p0 = g_ao + ((size_t)b * HW + (i0 + (q0 >> 2)) * WID + j0 + oxw + (q0 & 3)) * CH + head * HD;
            float* p1 = g_ao + ((size_t)b * HW + (i0 + (q1 >> 2)) * WID + j0 + oxw + (q1 & 3)) * CH + head * HD;
            p0[kp0] = tf32r(dT[mf][nf][0] * iv0);
            p1[kp0] = tf32r(dT[mf][nf][1] * iv1);
            p0[kp1] = tf32r(dT[mf][nf][2] * iv0);
            p1[kp1] = tf32r(dT[mf][nf][3] * iv1);
        }
    }
}

// =====================================================================
extern "C" void kernel_launch(void* const* d_in, const int* in_sizes, int n_in,
                              void* d_out, int out_size) {
    const float* x      = (const float*)d_in[0];
    const float* qkv_w  = (const float*)d_in[1];
    const float* rpb    = (const float*)d_in[2];
    const float* proj_w = (const float*)d_in[3];
    const float* proj_b = (const float*)d_in[4];
    float* out = (float*)d_out;

    cudaFuncSetAttribute(qkv_mma,  cudaFuncAttributeMaxDynamicSharedMemorySize, GEMM_SMEM_BYTES);
    cudaFuncSetAttribute(proj_mma, cudaFuncAttributeMaxDynamicSharedMemorySize, GEMM_SMEM_BYTES);
    cudaFuncSetAttribute(na_attn,  cudaFuncAttributeMaxDynamicSharedMemorySize, ATTN_SMEM);

    float* wq_d; cudaGetSymbolAddress((void**)&wq_d, g_wq);
    float* wp_d; cudaGetSymbolAddress((void**)&wp_d, g_wp);

    prep_w<<<(1536 * 512 + 255) / 256, 256>>>(qkv_w, wq_d, 1536 * 512);
    prep_w<<<(512 * 512 + 255) / 256, 256>>>(proj_w, wp_d, 512 * 512);
    xpose<<<dim3(HW / 32, CH / 32, BATCH), 256>>>(x);
    qkv_mma<<<dim3(1536 / 256, TOK / 128), 512, GEMM_SMEM_BYTES>>>(wq_d);
    na_attn<<<dim3(28, NH, BATCH), 128, ATTN_SMEM>>>(rpb);
    proj_mma<<<dim3(CH / 256, TOK / 128), 512, GEMM_SMEM_BYTES>>>(wp_d, proj_b, out);
}

// round 15
// speedup vs baseline: 3.8458x; 1.2471x over previous
#include <cuda_runtime.h>
#include <cuda_fp16.h>
#include <cstdint>
#include <math.h>

#define BATCH 8
#define CH    512
#define HGT   56
#define WID   56
#define HW    3136
#define NH    16
#define HD    32
#define TOK   25088
#define NKEY  49

__device__ float  g_q [(long)BATCH * NH * HW * HD];
__device__ float  g_k [(long)BATCH * NH * HW * HD];
__device__ float  g_v [(long)BATCH * NH * HW * HD];
__device__ __half g_ao[(long)TOK * CH];     // attention out, fp16, kperm16
__device__ __half g_xt[(long)TOK * CH];     // x token-major, fp16, kperm16
__device__ __half g_wq[(long)1536 * CH];
__device__ __half g_wp[(long)CH * CH];

// fp16 m16n8k16 k-permutation: lane q reads halves {2q,2q+1,2q+8,2q+9} contiguously
__device__ __forceinline__ int kperm16(int k) {
    const int p = (k >> 1) & 7;
    return (k & ~15) | ((p & 3) << 2) | ((p >> 2) << 1) | (k & 1);
}

__device__ __forceinline__ uint32_t smem_u32(const void* p) {
    uint32_t a;
    asm("{ .reg .u64 t; cvta.to.shared.u64 t, %1; cvt.u32.u64 %0, t; }" : "=r"(a) : "l"(p));
    return a;
}
__device__ __forceinline__ void cpasync16(uint32_t dst, const void* src) {
    asm volatile("cp.async.cg.shared.global [%0], [%1], 16;" :: "r"(dst), "l"(src));
}
#define CP_COMMIT() asm volatile("cp.async.commit_group;" ::: "memory")
__device__ __forceinline__ uint32_t to_tf32(float f) {
    uint32_t r;
    asm("cvt.rna.tf32.f32 %0, %1;" : "=r"(r) : "f"(f));
    return r;
}
__device__ __forceinline__ float tf32r(float f) { return __uint_as_float(to_tf32(f)); }

__device__ __forceinline__ void mma_tf32(float* c, const uint32_t* a, const uint32_t* b) {
    asm volatile(
        "mma.sync.aligned.m16n8k8.row.col.f32.tf32.tf32.f32 "
        "{%0,%1,%2,%3}, {%4,%5,%6,%7}, {%8,%9}, {%0,%1,%2,%3};"
        : "+f"(c[0]), "+f"(c[1]), "+f"(c[2]), "+f"(c[3])
        : "r"(a[0]), "r"(a[1]), "r"(a[2]), "r"(a[3]), "r"(b[0]), "r"(b[1]));
}
__device__ __forceinline__ void mma_f16(float* c, const uint32_t* a, const uint32_t* b) {
    asm volatile(
        "mma.sync.aligned.m16n8k16.row.col.f32.f16.f16.f32 "
        "{%0,%1,%2,%3}, {%4,%5,%6,%7}, {%8,%9}, {%0,%1,%2,%3};"
        : "+f"(c[0]), "+f"(c[1]), "+f"(c[2]), "+f"(c[3])
        : "r"(a[0]), "r"(a[1]), "r"(a[2]), "r"(a[3]), "r"(b[0]), "r"(b[1]));
}

// =====================================================================
__global__ __launch_bounds__(256) void prep_w(const float* __restrict__ src,
                                              __half* __restrict__ dst, int total) {
    const int i = blockIdx.x * 256 + threadIdx.x;
    if (i < total) {
        const int k = i & 511;
        const int n = i >> 9;
        dst[(n << 9) | kperm16(k)] = __float2half_rn(src[i]);
    }
}

__global__ __launch_bounds__(256) void xpose(const float* __restrict__ x) {
    __shared__ float t[32][33];
    const int b  = blockIdx.z;
    const int p0 = blockIdx.x * 32;
    const int c0 = blockIdx.y * 32;
    const int tx = threadIdx.x & 31;
    const int ty = threadIdx.x >> 5;
    const float* src = x + ((size_t)b * CH + c0) * HW + p0;
#pragma unroll
    for (int k = 0; k < 4; ++k) t[ty + 8 * k][tx] = src[(size_t)(ty + 8 * k) * HW + tx];
    __syncthreads();
    __half* dst = g_xt + ((size_t)b * HW + p0) * CH + c0;
    const int pp = kperm16(tx & 15) | (tx & 16);
#pragma unroll
    for (int k = 0; k < 4; ++k)
        dst[(size_t)(ty + 8 * k) * CH + pp] = __float2half_rn(t[tx][ty + 8 * k]);
}

// =====================================================================
// fp16 GEMM: CTA 128m x 256n, 512 thr (16 warps of 32x64), KT=32 halves,
// 3-stage cp.async ring. Row stride 48 halves (96B) — conflict-free LDS.64.
// =====================================================================
#define KT 32
#define RSH 48
#define A_BYT16 (128 * RSH * 2)            // 12288
#define B_BYT16 (256 * RSH * 2)            // 24576
#define STG_BYTES (A_BYT16 + B_BYT16)      // 36864
#define GEMM_SMEM_BYTES (3 * STG_BYTES)    // 110592

__device__ __forceinline__ void g_compute(const char* smc, float acc[2][8][4],
                                          int lane, int wm, int wn) {
    const char* Asb = smc;
    const char* Bsb = smc + A_BYT16;
    const int mrow = lane >> 2;
    const int qb = (lane & 3) * 8;
#pragma unroll
    for (int ks = 0; ks < 2; ++ks) {
        const int cob = ks * 32 + qb;
        uint32_t a[2][4];
#pragma unroll
        for (int mt = 0; mt < 2; ++mt) {
            const int m = wm + mt * 16 + mrow;
            const uint2 lo = *(const uint2*)(Asb + m * (RSH * 2) + cob);
            const uint2 hi = *(const uint2*)(Asb + (m + 8) * (RSH * 2) + cob);
            a[mt][0] = lo.x; a[mt][1] = hi.x; a[mt][2] = lo.y; a[mt][3] = hi.y;
        }
        uint32_t b[8][2];
#pragma unroll
        for (int nt = 0; nt < 8; ++nt) {
            const uint2 bv = *(const uint2*)(Bsb + (wn + nt * 8 + mrow) * (RSH * 2) + cob);
            b[nt][0] = bv.x; b[nt][1] = bv.y;
        }
#pragma unroll
        for (int mt = 0; mt < 2; ++mt)
#pragma unroll
            for (int nt = 0; nt < 8; ++nt) mma_f16(acc[mt][nt], a[mt], b[nt]);
    }
}

__device__ __forceinline__ void g_mainloop(char* dynsm, float acc[2][8][4],
                                           const __half* __restrict__ Ap,
                                           const __half* __restrict__ Bp,
                                           int m0, int n0) {
    const int tid  = threadIdx.x;
    const int lane = tid & 31, wid = tid >> 5;
    const int wm = (wid & 3) * 32, wn = (wid >> 2) * 64;
#pragma unroll
    for (int mt = 0; mt < 2; ++mt)
#pragma unroll
        for (int nt = 0; nt < 8; ++nt)
#pragma unroll
            for (int r = 0; r < 4; ++r) acc[mt][nt][r] = 0.f;

    const int r0  = tid >> 2;            // 0..127
    const int ch8 = (tid & 3) * 8;       // halves (16B chunks)
    const uint32_t offA  = (uint32_t)(r0 * (RSH * 2) + (tid & 3) * 16);
    const uint32_t offB0 = offA + A_BYT16;
    const uint32_t offB1 = (uint32_t)((r0 + 128) * (RSH * 2) + (tid & 3) * 16) + A_BYT16;
    const __half* gA  = Ap + (size_t)(m0 + r0) * CH + ch8;
    const __half* gB0 = Bp + (size_t)(n0 + r0) * CH + ch8;
    const __half* gB1 = Bp + (size_t)(n0 + r0 + 128) * CH + ch8;

    const uint32_t sb0 = smem_u32(dynsm);
    const uint32_t sb1 = sb0 + STG_BYTES;
    const uint32_t sb2 = sb0 + 2 * STG_BYTES;

#define G_LOAD(base, k0) do { \
        cpasync16((base) + offA,  gA  + (k0)); \
        cpasync16((base) + offB0, gB0 + (k0)); \
        cpasync16((base) + offB1, gB1 + (k0)); \
        CP_COMMIT(); } while (0)

    G_LOAD(sb0, 0);
    G_LOAD(sb1, KT);

    const int NT = CH / KT;   // 16
    uint32_t cur = sb0, nxt = sb1, fut = sb2;

#pragma unroll 3
    for (int t = 0; t < NT; ++t) {
        if (t < NT - 1) asm volatile("cp.async.wait_group 1;" ::: "memory");
        else            asm volatile("cp.async.wait_group 0;" ::: "memory");
        __syncthreads();
        if (t + 2 < NT) G_LOAD(fut, (t + 2) * KT);
        g_compute(dynsm + (cur - sb0), acc, lane, wm, wn);
        const uint32_t tmp = cur; cur = nxt; nxt = fut; fut = tmp;
    }
#undef G_LOAD
}

__global__ __launch_bounds__(512) void qkv_mma(const __half* __restrict__ w) {
    extern __shared__ char dynsm[];
    float acc[2][8][4];
    const int n0 = blockIdx.x * 256;
    const int m0 = blockIdx.y * 128;
    g_mainloop(dynsm, acc, g_xt, w, m0, n0);

    const int lane = threadIdx.x & 31, wid = threadIdx.x >> 5;
    const int wm = (wid & 3) * 32, wn = (wid >> 2) * 64;
    const int which = n0 >> 9;
    float* outp = (which == 0) ? g_q : (which == 1) ? g_k : g_v;
    const float sc = (which == 0) ? 0.17677669529663687f : 1.0f;

#pragma unroll
    for (int mt = 0; mt < 2; ++mt) {
        const int mA = m0 + wm + mt * 16 + (lane >> 2);
        const int bA = mA / HW, pA = mA - bA * HW;
        const int mB = mA + 8;
        const int bB = mB / HW, pB = mB - bB * HW;
#pragma unroll
        for (int nt = 0; nt < 8; ++nt) {
            const int n  = n0 + wn + nt * 8 + 2 * (lane & 3);
            const int nl = n & 511;
            const int head = nl >> 5, d = nl & 31;
            float2 v0 = make_float2(tf32r(acc[mt][nt][0] * sc), tf32r(acc[mt][nt][1] * sc));
            float2 v1 = make_float2(tf32r(acc[mt][nt][2] * sc), tf32r(acc[mt][nt][3] * sc));
            *(float2*)&outp[((size_t)(bA * NH + head) * HW + pA) * HD + d] = v0;
            *(float2*)&outp[((size_t)(bB * NH + head) * HW + pB) * HD + d] = v1;
        }
    }
}

__global__ __launch_bounds__(512) void proj_mma(const __half* __restrict__ w,
                                                const float* __restrict__ bias,
                                                float* __restrict__ out) {
    extern __shared__ char dynsm[];
    float acc[2][8][4];
    const int n0 = blockIdx.x * 256;
    const int m0 = blockIdx.y * 128;
    g_mainloop(dynsm, acc, g_ao, w, m0, n0);

    const int lane = threadIdx.x & 31, wid = threadIdx.x >> 5;
    const int wm = (wid & 3) * 32, wn = (wid >> 2) * 64;

#pragma unroll
    for (int mt = 0; mt < 2; ++mt) {
        const int mA = m0 + wm + mt * 16 + (lane >> 2);
        const int bA = mA / HW, pA = mA - bA * HW;
        const int mB = mA + 8;
        const int bB = mB / HW, pB = mB - bB * HW;
#pragma unroll
        for (int nt = 0; nt < 8; ++nt) {
            const int n = n0 + wn + nt * 8 + 2 * (lane & 3);
            const float b0 = __ldg(&bias[n]), b1 = __ldg(&bias[n + 1]);
            out[((size_t)bA * CH + n) * HW + pA]     = acc[mt][nt][0] + b0;
            out[((size_t)bA * CH + n + 1) * HW + pA] = acc[mt][nt][1] + b1;
            out[((size_t)bB * CH + n) * HW + pB]     = acc[mt][nt][2] + b0;
            out[((size_t)bB * CH + n + 1) * HW + pB] = acc[mt][nt][3] + b1;
        }
    }
}

// =====================================================================
// MMA neighborhood attention (tf32, unchanged; g_ao fp16 kperm16 store)
// =====================================================================
#define AHI 14
#define AHJ 22
#define AROWS (AHI * AHJ)
#define AP 36
#define ACH 18
#define ATTN_SMEM ((2 * AROWS * AP + 176 + 128 + 144) * 4)

__global__ __launch_bounds__(128) void na_attn(const float* __restrict__ rpb) {
    extern __shared__ float asmem[];
    float* Ks     = asmem;
    float* Vs     = Ks + AROWS * AP;
    float* rpbs   = Vs + AROWS * AP;
    float* normsm = rpbs + 176;
    int*   tbl    = (int*)(normsm + 128);

    const unsigned FULL = 0xffffffffu;
    const int tid = threadIdx.x, lane = tid & 31, warp = tid >> 5;
    const int tile = blockIdx.x, head = blockIdx.y, b = blockIdx.z;
    const int ti = tile >> 2, jt = tile & 3;
    const int i0 = ti * 8;
    const int j0 = (jt < 3) ? jt * 16 : 40;
    const int base_i = max(i0 - 3, 0);
    const int base_j = max(j0 - 3, 0);
    const int bh = b * NH + head;

    const float4* kg = (const float4*)(g_k + (size_t)bh * HW * HD);
    const float4* vg = (const float4*)(g_v + (size_t)bh * HW * HD);
    float4* Ks4 = (float4*)Ks;
    float4* Vs4 = (float4*)Vs;
    for (int idx = tid; idx < AROWS * 8; idx += 128) {
        const int row = idx >> 3, wq = idx & 7;
        const int ry = row / AHJ, rx = row - ry * AHJ;
        const int gi = min(base_i + ry, HGT - 1);
        const int gj = min(base_j + rx, WID - 1);
        const int g = (gi * WID + gj) * 8 + wq;
        Ks4[row * (AP / 4) + wq] = kg[g];
        Vs4[row * (AP / 4) + wq] = vg[g];
    }
    for (int idx = tid; idx < 169; idx += 128) rpbs[idx] = rpb[head * 169 + idx];
    for (int t = tid; t < 144; t += 128) {
        const int ry = t / 10, rx = t - ry * 10;
        tbl[t] = ry | (rx << 8) | ((ry * 13 + rx) << 16);
    }

    const int oxw = warp * 4;
    const int minsj = min(max(j0 + oxw - 3, 0), WID - 7);
    const int wcol0 = minsj - base_j;

    int ryq[4], rxq[4], CBr[4];
#pragma unroll
    for (int s = 0; s < 4; ++s) {
        const int m = (s >> 1) * 16 + (s & 1) * 8 + (lane >> 2);
        const int qy = m >> 2, qxl = m & 3;
        const int i = i0 + qy, j = j0 + oxw + qxl;
        const int si = min(max(i - 3, 0), HGT - 7);
        const int sj = min(max(j - 3, 0), WID - 7);
        ryq[s] = si - base_i;
        rxq[s] = sj - minsj;
        CBr[s] = (base_i - i + 6) * 13 + (minsj - j + 6);
    }

    uint32_t qa[2][4][4];
    {
        const float* qbase = g_q + (size_t)bh * HW * HD;
        const float* qrow[4];
#pragma unroll
        for (int h = 0; h < 4; ++h) {
            const int m = (h >> 1) * 16 + (h & 1) * 8 + (lane >> 2);
            qrow[h] = qbase + (size_t)((i0 + (m >> 2)) * WID + j0 + oxw + (m & 3)) * HD;
        }
#pragma unroll
        for (int mf = 0; mf < 2; ++mf)
#pragma unroll
            for (int kf = 0; kf < 4; ++kf) {
                const int k0 = kf * 8 + (lane & 3);
                qa[mf][kf][0] = __float_as_uint(__ldg(qrow[mf * 2] + k0));
                qa[mf][kf][1] = __float_as_uint(__ldg(qrow[mf * 2 + 1] + k0));
                qa[mf][kf][2] = __float_as_uint(__ldg(qrow[mf * 2] + k0 + 4));
                qa[mf][kf][3] = __float_as_uint(__ldg(qrow[mf * 2 + 1] + k0 + 4));
            }
    }
    __syncthreads();

    float dT[2][4][4];
#pragma unroll
    for (int mf = 0; mf < 2; ++mf)
#pragma unroll
        for (int nf = 0; nf < 4; ++nf)
#pragma unroll
            for (int r = 0; r < 4; ++r) dT[mf][nf][r] = 0.f;
    float norm[4] = {0.f, 0.f, 0.f, 0.f};

    const int srcA = (lane & ~3) | ((lane & 3) >> 1);
    const int srcB = srcA | 2;

#pragma unroll 2
    for (int ch = 0; ch < ACH; ++ch) {
        float c[2][4] = {{0.f, 0.f, 0.f, 0.f}, {0.f, 0.f, 0.f, 0.f}};
        {
            const int tb = min(ch * 8 + (lane >> 2), 139);
            const int e = tbl[tb];
            const int srow = (e & 255) * AHJ + ((e >> 8) & 255) + wcol0;
            const float* kr = Ks + srow * AP;
#pragma unroll
            for (int kf = 0; kf < 4; ++kf) {
                uint32_t bb[2];
                bb[0] = __float_as_uint(kr[kf * 8 + (lane & 3)]);
                bb[1] = __float_as_uint(kr[kf * 8 + 4 + (lane & 3)]);
                mma_tf32(c[0], qa[0][kf], bb);
                mma_tf32(c[1], qa[1][kf], bb);
            }
        }
        float p[2][4];
        {
            const int t0 = ch * 8 + 2 * (lane & 3);
            const int ec0 = tbl[min(t0, 139)];
            const int ec1 = tbl[min(t0 + 1, 139)];
#pragma unroll
            for (int cc = 0; cc < 2; ++cc) {
                const int e = cc ? ec1 : ec0;
                const int ry = e & 255, rx = (e >> 8) & 255, r13 = e >> 16;
                const bool tv = (t0 + cc) < 140;
#pragma unroll
                for (int s = 0; s < 4; ++s) {
                    const int mf = s >> 1, rh = s & 1;
                    const float cv = c[mf][rh * 2 + cc];
                    const bool v = tv && ((unsigned)(ry - ryq[s]) <= 6u)
                                      && ((unsigned)(rx - rxq[s]) <= 6u);
                    int bi = r13 + CBr[s];
                    bi = max(min(bi, 168), 0);
                    float ev = v ? __expf(cv + rpbs[bi]) : 0.f;
                    ev = tf32r(ev);
                    p[mf][rh * 2 + cc] = ev;
                    norm[s] += ev;
                }
            }
        }
        {
            const int ea = tbl[min(ch * 8 + (lane & 3), 139)];
            const int eb = tbl[min(ch * 8 + 4 + (lane & 3), 139)];
            const int ra = (ea & 255) * AHJ + ((ea >> 8) & 255) + wcol0;
            const int rb = (eb & 255) * AHJ + ((eb >> 8) & 255) + wcol0;
            const float* v0 = Vs + ra * AP;
            const float* v4 = Vs + rb * AP;
            uint32_t av[2][4];
#pragma unroll
            for (int mf = 0; mf < 2; ++mf) {
                const int d0 = mf * 16 + (lane >> 2);
                av[mf][0] = __float_as_uint(v0[d0]);
                av[mf][1] = __float_as_uint(v0[d0 + 8]);
                av[mf][2] = __float_as_uint(v4[d0]);
                av[mf][3] = __float_as_uint(v4[d0 + 8]);
            }
#pragma unroll
            for (int nf = 0; nf < 4; ++nf) {
                const float va0 = p[nf >> 1][(nf & 1) * 2];
                const float va1 = p[nf >> 1][(nf & 1) * 2 + 1];
                const float s0 = __shfl_sync(FULL, va0, srcA);
                const float s1 = __shfl_sync(FULL, va1, srcA);
                const float u0 = __shfl_sync(FULL, va0, srcB);
                const float u1 = __shfl_sync(FULL, va1, srcB);
                uint32_t bb[2];
                bb[0] = __float_as_uint((lane & 1) ? s1 : s0);
                bb[1] = __float_as_uint((lane & 1) ? u1 : u0);
                mma_tf32(dT[0][nf], av[0], bb);
                mma_tf32(dT[1][nf], av[1], bb);
            }
        }
    }

#pragma unroll
    for (int s = 0; s < 4; ++s) {
        float n = norm[s];
        n += __shfl_xor_sync(FULL, n, 1);
        n += __shfl_xor_sync(FULL, n, 2);
        if ((lane & 3) == 0)
            normsm[warp * 32 + (s >> 1) * 16 + (s & 1) * 8 + (lane >> 2)] = 1.f / n;
    }
    __syncwarp();

    const int dlo = lane >> 2;
#pragma unroll
    for (int mf = 0; mf < 2; ++mf) {
        const int d0 = mf * 16 + dlo, d1 = d0 + 8;
        const int kp0 = kperm16(d0), kp1 = kperm16(d1);
#pragma unroll
        for (int nf = 0; nf < 4; ++nf) {
            const int q0 = nf * 8 + 2 * (lane & 3), q1 = q0 + 1;
            const float iv0 = normsm[warp * 32 + q0];
            const float iv1 = normsm[warp * 32 + q1];
            __half* p0 = g_ao + ((size_t)b * HW + (i0 + (q0 >> 2)) * WID + j0 + oxw + (q0 & 3)) * CH + head * HD;
            __half* p1 = g_ao + ((size_t)b * HW + (i0 + (q1 >> 2)) * WID + j0 + oxw + (q1 & 3)) * CH + head * HD;
            p0[kp0] = __float2half_rn(dT[mf][nf][0] * iv0);
            p1[kp0] = __float2half_rn(dT[mf][nf][1] * iv1);
            p0[kp1] = __float2half_rn(dT[mf][nf][2] * iv0);
            p1[kp1] = __float2half_rn(dT[mf][nf][3] * iv1);
        }
    }
}

// =====================================================================
extern "C" void kernel_launch(void* const* d_in, const int* in_sizes, int n_in,
                              void* d_out, int out_size) {
    const float* x      = (const float*)d_in[0];
    const float* qkv_w  = (const float*)d_in[1];
    const float* rpb    = (const float*)d_in[2];
    const float* proj_w = (const float*)d_in[3];
    const float* proj_b = (const float*)d_in[4];
    float* out = (float*)d_out;

    cudaFuncSetAttribute(qkv_mma,  cudaFuncAttributeMaxDynamicSharedMemorySize, GEMM_SMEM_BYTES);
    cudaFuncSetAttribute(proj_mma, cudaFuncAttributeMaxDynamicSharedMemorySize, GEMM_SMEM_BYTES);
    cudaFuncSetAttribute(na_attn,  cudaFuncAttributeMaxDynamicSharedMemorySize, ATTN_SMEM);

    __half* wq_d; cudaGetSymbolAddress((void**)&wq_d, g_wq);
    __half* wp_d; cudaGetSymbolAddress((void**)&wp_d, g_wp);

    prep_w<<<(1536 * 512 + 255) / 256, 256>>>(qkv_w, wq_d, 1536 * 512);
    prep_w<<<(512 * 512 + 255) / 256, 256>>>(proj_w, wp_d, 512 * 512);
    xpose<<<dim3(HW / 32, CH / 32, BATCH), 256>>>(x);
    qkv_mma<<<dim3(1536 / 256, TOK / 128), 512, GEMM_SMEM_BYTES>>>(wq_d);
    na_attn<<<dim3(28, NH, BATCH), 128, ATTN_SMEM>>>(rpb);
    proj_mma<<<dim3(CH / 256, TOK / 128), 512, GEMM_SMEM_BYTES>>>(wp_d, proj_b, out);
}

// round 16
// speedup vs baseline: 5.0921x; 1.3241x over previous
#include <cuda_runtime.h>
#include <cuda_fp16.h>
#include <cstdint>
#include <math.h>

#define BATCH 8
#define CH    512
#define HGT   56
#define WID   56
#define HW    3136
#define NH    16
#define HD    32
#define TOK   25088
#define NKEY  49

__device__ float  g_q [(long)BATCH * NH * HW * HD];
__device__ float  g_k [(long)BATCH * NH * HW * HD];
__device__ float  g_v [(long)BATCH * NH * HW * HD];
__device__ __half g_ao[(long)TOK * CH];     // attention out, fp16, kperm16
__device__ __half g_xt[(long)TOK * CH];     // x token-major, fp16, kperm16
__device__ __half g_wq[(long)1536 * CH];
__device__ __half g_wp[(long)CH * CH];

// fp16 m16n8k16 k-permutation: lane q reads halves {2q,2q+1,2q+8,2q+9} contiguously
__device__ __forceinline__ int kperm16(int k) {
    const int p = (k >> 1) & 7;
    return (k & ~15) | ((p & 3) << 2) | ((p >> 2) << 1) | (k & 1);
}

__device__ __forceinline__ uint32_t smem_u32(const void* p) {
    uint32_t a;
    asm("{ .reg .u64 t; cvta.to.shared.u64 t, %1; cvt.u32.u64 %0, t; }" : "=r"(a) : "l"(p));
    return a;
}
__device__ __forceinline__ void cpasync16(uint32_t dst, const void* src) {
    asm volatile("cp.async.cg.shared.global [%0], [%1], 16;" :: "r"(dst), "l"(src));
}
#define CP_COMMIT() asm volatile("cp.async.commit_group;" ::: "memory")
__device__ __forceinline__ uint32_t to_tf32(float f) {
    uint32_t r;
    asm("cvt.rna.tf32.f32 %0, %1;" : "=r"(r) : "f"(f));
    return r;
}
__device__ __forceinline__ float tf32r(float f) { return __uint_as_float(to_tf32(f)); }
__device__ __forceinline__ uint32_t packh2(float lo, float hi) {
    const __half2 h = __floats2half2_rn(lo, hi);
    return *(const uint32_t*)&h;
}
__device__ __forceinline__ uint32_t packhh(__half lo, __half hi) {
    const __half2 h = __halves2half2(lo, hi);
    return *(const uint32_t*)&h;
}

__device__ __forceinline__ void mma_f16(float* c, const uint32_t* a, const uint32_t* b) {
    asm volatile(
        "mma.sync.aligned.m16n8k16.row.col.f32.f16.f16.f32 "
        "{%0,%1,%2,%3}, {%4,%5,%6,%7}, {%8,%9}, {%0,%1,%2,%3};"
        : "+f"(c[0]), "+f"(c[1]), "+f"(c[2]), "+f"(c[3])
        : "r"(a[0]), "r"(a[1]), "r"(a[2]), "r"(a[3]), "r"(b[0]), "r"(b[1]));
}

// =====================================================================
__global__ __launch_bounds__(256) void prep_w(const float* __restrict__ src,
                                              __half* __restrict__ dst, int total) {
    const int i = blockIdx.x * 256 + threadIdx.x;
    if (i < total) {
        const int k = i & 511;
        const int n = i >> 9;
        dst[(n << 9) | kperm16(k)] = __float2half_rn(src[i]);
    }
}

__global__ __launch_bounds__(256) void xpose(const float* __restrict__ x) {
    __shared__ float t[32][33];
    const int b  = blockIdx.z;
    const int p0 = blockIdx.x * 32;
    const int c0 = blockIdx.y * 32;
    const int tx = threadIdx.x & 31;
    const int ty = threadIdx.x >> 5;
    const float* src = x + ((size_t)b * CH + c0) * HW + p0;
#pragma unroll
    for (int k = 0; k < 4; ++k) t[ty + 8 * k][tx] = src[(size_t)(ty + 8 * k) * HW + tx];
    __syncthreads();
    __half* dst = g_xt + ((size_t)b * HW + p0) * CH + c0;
    const int pp = kperm16(tx & 15) | (tx & 16);
#pragma unroll
    for (int k = 0; k < 4; ++k)
        dst[(size_t)(ty + 8 * k) * CH + pp] = __float2half_rn(t[tx][ty + 8 * k]);
}

// =====================================================================
// fp16 GEMM (unchanged, known-good): CTA 128m x 256n, KT=32, 3-stage ring
// =====================================================================
#define KT 32
#define RSH 48
#define A_BYT16 (128 * RSH * 2)
#define B_BYT16 (256 * RSH * 2)
#define STG_BYTES (A_BYT16 + B_BYT16)
#define GEMM_SMEM_BYTES (3 * STG_BYTES)

__device__ __forceinline__ void g_compute(const char* smc, float acc[2][8][4],
                                          int lane, int wm, int wn) {
    const char* Asb = smc;
    const char* Bsb = smc + A_BYT16;
    const int mrow = lane >> 2;
    const int qb = (lane & 3) * 8;
#pragma unroll
    for (int ks = 0; ks < 2; ++ks) {
        const int cob = ks * 32 + qb;
        uint32_t a[2][4];
#pragma unroll
        for (int mt = 0; mt < 2; ++mt) {
            const int m = wm + mt * 16 + mrow;
            const uint2 lo = *(const uint2*)(Asb + m * (RSH * 2) + cob);
            const uint2 hi = *(const uint2*)(Asb + (m + 8) * (RSH * 2) + cob);
            a[mt][0] = lo.x; a[mt][1] = hi.x; a[mt][2] = lo.y; a[mt][3] = hi.y;
        }
        uint32_t b[8][2];
#pragma unroll
        for (int nt = 0; nt < 8; ++nt) {
            const uint2 bv = *(const uint2*)(Bsb + (wn + nt * 8 + mrow) * (RSH * 2) + cob);
            b[nt][0] = bv.x; b[nt][1] = bv.y;
        }
#pragma unroll
        for (int mt = 0; mt < 2; ++mt)
#pragma unroll
            for (int nt = 0; nt < 8; ++nt) mma_f16(acc[mt][nt], a[mt], b[nt]);
    }
}

__device__ __forceinline__ void g_mainloop(char* dynsm, float acc[2][8][4],
                                           const __half* __restrict__ Ap,
                                           const __half* __restrict__ Bp,
                                           int m0, int n0) {
    const int tid  = threadIdx.x;
    const int lane = tid & 31, wid = tid >> 5;
    const int wm = (wid & 3) * 32, wn = (wid >> 2) * 64;
#pragma unroll
    for (int mt = 0; mt < 2; ++mt)
#pragma unroll
        for (int nt = 0; nt < 8; ++nt)
#pragma unroll
            for (int r = 0; r < 4; ++r) acc[mt][nt][r] = 0.f;

    const int r0  = tid >> 2;
    const int ch8 = (tid & 3) * 8;
    const uint32_t offA  = (uint32_t)(r0 * (RSH * 2) + (tid & 3) * 16);
    const uint32_t offB0 = offA + A_BYT16;
    const uint32_t offB1 = (uint32_t)((r0 + 128) * (RSH * 2) + (tid & 3) * 16) + A_BYT16;
    const __half* gA  = Ap + (size_t)(m0 + r0) * CH + ch8;
    const __half* gB0 = Bp + (size_t)(n0 + r0) * CH + ch8;
    const __half* gB1 = Bp + (size_t)(n0 + r0 + 128) * CH + ch8;

    const uint32_t sb0 = smem_u32(dynsm);
    const uint32_t sb1 = sb0 + STG_BYTES;
    const uint32_t sb2 = sb0 + 2 * STG_BYTES;

#define G_LOAD(base, k0) do { \
        cpasync16((base) + offA,  gA  + (k0)); \
        cpasync16((base) + offB0, gB0 + (k0)); \
        cpasync16((base) + offB1, gB1 + (k0)); \
        CP_COMMIT(); } while (0)

    G_LOAD(sb0, 0);
    G_LOAD(sb1, KT);

    const int NT = CH / KT;
    uint32_t cur = sb0, nxt = sb1, fut = sb2;

#pragma unroll 3
    for (int t = 0; t < NT; ++t) {
        if (t < NT - 1) asm volatile("cp.async.wait_group 1;" ::: "memory");
        else            asm volatile("cp.async.wait_group 0;" ::: "memory");
        __syncthreads();
        if (t + 2 < NT) G_LOAD(fut, (t + 2) * KT);
        g_compute(dynsm + (cur - sb0), acc, lane, wm, wn);
        const uint32_t tmp = cur; cur = nxt; nxt = fut; fut = tmp;
    }
#undef G_LOAD
}

__global__ __launch_bounds__(512) void qkv_mma(const __half* __restrict__ w) {
    extern __shared__ char dynsm[];
    float acc[2][8][4];
    const int n0 = blockIdx.x * 256;
    const int m0 = blockIdx.y * 128;
    g_mainloop(dynsm, acc, g_xt, w, m0, n0);

    const int lane = threadIdx.x & 31, wid = threadIdx.x >> 5;
    const int wm = (wid & 3) * 32, wn = (wid >> 2) * 64;
    const int which = n0 >> 9;
    float* outp = (which == 0) ? g_q : (which == 1) ? g_k : g_v;
    const float sc = (which == 0) ? 0.17677669529663687f : 1.0f;

#pragma unroll
    for (int mt = 0; mt < 2; ++mt) {
        const int mA = m0 + wm + mt * 16 + (lane >> 2);
        const int bA = mA / HW, pA = mA - bA * HW;
        const int mB = mA + 8;
        const int bB = mB / HW, pB = mB - bB * HW;
#pragma unroll
        for (int nt = 0; nt < 8; ++nt) {
            const int n  = n0 + wn + nt * 8 + 2 * (lane & 3);
            const int nl = n & 511;
            const int head = nl >> 5, d = nl & 31;
            float2 v0 = make_float2(tf32r(acc[mt][nt][0] * sc), tf32r(acc[mt][nt][1] * sc));
            float2 v1 = make_float2(tf32r(acc[mt][nt][2] * sc), tf32r(acc[mt][nt][3] * sc));
            *(float2*)&outp[((size_t)(bA * NH + head) * HW + pA) * HD + d] = v0;
            *(float2*)&outp[((size_t)(bB * NH + head) * HW + pB) * HD + d] = v1;
        }
    }
}

__global__ __launch_bounds__(512) void proj_mma(const __half* __restrict__ w,
                                                const float* __restrict__ bias,
                                                float* __restrict__ out) {
    extern __shared__ char dynsm[];
    float acc[2][8][4];
    const int n0 = blockIdx.x * 256;
    const int m0 = blockIdx.y * 128;
    g_mainloop(dynsm, acc, g_ao, w, m0, n0);

    const int lane = threadIdx.x & 31, wid = threadIdx.x >> 5;
    const int wm = (wid & 3) * 32, wn = (wid >> 2) * 64;

#pragma unroll
    for (int mt = 0; mt < 2; ++mt) {
        const int mA = m0 + wm + mt * 16 + (lane >> 2);
        const int bA = mA / HW, pA = mA - bA * HW;
        const int mB = mA + 8;
        const int bB = mB / HW, pB = mB - bB * HW;
#pragma unroll
        for (int nt = 0; nt < 8; ++nt) {
            const int n = n0 + wn + nt * 8 + 2 * (lane & 3);
            const float b0 = __ldg(&bias[n]), b1 = __ldg(&bias[n + 1]);
            out[((size_t)bA * CH + n) * HW + pA]     = acc[mt][nt][0] + b0;
            out[((size_t)bA * CH + n + 1) * HW + pA] = acc[mt][nt][1] + b1;
            out[((size_t)bB * CH + n) * HW + pB]     = acc[mt][nt][2] + b0;
            out[((size_t)bB * CH + n + 1) * HW + pB] = acc[mt][nt][3] + b1;
        }
    }
}

// =====================================================================
// fp16 MMA neighborhood attention.
// K/V staged fp16+kperm16 (49KB -> 4 CTAs/SM). Chunks of 16 keys via
// m16n8k16: QK (4 LDS.64 + 8 mma) -> mask/exp -> P packs straight into
// AV B-frags (no shuffles) -> AV (16 LDS.16 + 8 mma).
// =====================================================================
#define AHI 14
#define AHJ 22
#define AROWS (AHI * AHJ)   // 308
#define RSA 40              // halves per K/V row
#define ATTN_SMEM (2 * AROWS * RSA * 2 + (176 + 128 + 144) * 4)

__global__ __launch_bounds__(128) void na_attn(const float* __restrict__ rpb) {
    extern __shared__ char asmc[];
    __half* Ks    = (__half*)asmc;
    __half* Vs    = Ks + AROWS * RSA;
    float* rpbs   = (float*)(Vs + AROWS * RSA);   // 176
    float* normsm = rpbs + 176;                   // 128
    int*   tbl    = (int*)(normsm + 128);         // 144

    const unsigned FULL = 0xffffffffu;
    const int tid = threadIdx.x, lane = tid & 31, warp = tid >> 5;
    const int qq = lane & 3, g = lane >> 2;
    const int tile = blockIdx.x, head = blockIdx.y, b = blockIdx.z;
    const int ti = tile >> 2, jt = tile & 3;
    const int i0 = ti * 8;
    const int j0 = (jt < 3) ? jt * 16 : 40;
    const int base_i = max(i0 - 3, 0);
    const int base_j = max(j0 - 3, 0);
    const int bh = b * NH + head;

    // ---- halo staging: fp32 -> fp16 with kperm16 pair placement ----
    const float4* kg = (const float4*)(g_k + (size_t)bh * HW * HD);
    const float4* vg = (const float4*)(g_v + (size_t)bh * HW * HD);
    for (int idx = tid; idx < AROWS * 8; idx += 128) {
        const int row = idx >> 3, wq = idx & 7;
        const int ry = row / AHJ, rx = row - ry * AHJ;
        const int gi = min(base_i + ry, HGT - 1);
        const int gj = min(base_j + rx, WID - 1);
        const int gofs = (gi * WID + gj) * 8 + wq;
        const float4 kf = kg[gofs];
        const float4 vf = vg[gofs];
        const int grp = (4 * wq) & 16;
        const int p0 = (2 * wq) & 7, p1 = (2 * wq + 1) & 7;
        const int off0 = grp + 4 * (p0 & 3) + 2 * (p0 >> 2);
        const int off1 = grp + 4 * (p1 & 3) + 2 * (p1 >> 2);
        *(__half2*)&Ks[row * RSA + off0] = __floats2half2_rn(kf.x, kf.y);
        *(__half2*)&Ks[row * RSA + off1] = __floats2half2_rn(kf.z, kf.w);
        *(__half2*)&Vs[row * RSA + off0] = __floats2half2_rn(vf.x, vf.y);
        *(__half2*)&Vs[row * RSA + off1] = __floats2half2_rn(vf.z, vf.w);
    }
    for (int idx = tid; idx < 169; idx += 128) rpbs[idx] = rpb[head * 169 + idx];
    for (int t = tid; t < 144; t += 128) {
        const int ry = t / 10, rx = t - ry * 10;
        tbl[t] = ry | (rx << 8) | ((ry * 13 + rx) << 16);
    }

    const int oxw = warp * 4;
    const int minsj = min(max(j0 + oxw - 3, 0), WID - 7);
    const int wcol0 = minsj - base_j;

    int ryq[4], rxq[4], CBr[4];
#pragma unroll
    for (int s = 0; s < 4; ++s) {
        const int m = (s >> 1) * 16 + (s & 1) * 8 + g;
        const int qy = m >> 2, qxl = m & 3;
        const int i = i0 + qy, j = j0 + oxw + qxl;
        const int si = min(max(i - 3, 0), HGT - 7);
        const int sj = min(max(j - 3, 0), WID - 7);
        ryq[s] = si - base_i;
        rxq[s] = sj - minsj;
        CBr[s] = (base_i - i + 6) * 13 + (minsj - j + 6);
    }

    // ---- Q A-frags (fp16) from gmem ----
    uint32_t qa[2][2][4];
    {
        const float* qbase = g_q + (size_t)bh * HW * HD;
        const float* qrow[4];
#pragma unroll
        for (int h = 0; h < 4; ++h) {
            const int m = (h >> 1) * 16 + (h & 1) * 8 + g;
            qrow[h] = qbase + (size_t)((i0 + (m >> 2)) * WID + j0 + oxw + (m & 3)) * HD;
        }
#pragma unroll
        for (int mf = 0; mf < 2; ++mf)
#pragma unroll
            for (int ks = 0; ks < 2; ++ks) {
                const float* r0p = qrow[mf * 2]     + ks * 16;
                const float* r1p = qrow[mf * 2 + 1] + ks * 16;
                const float2 x0 = *(const float2*)(r0p + 2 * qq);
                const float2 x1 = *(const float2*)(r1p + 2 * qq);
                const float2 x2 = *(const float2*)(r0p + 2 * qq + 8);
                const float2 x3 = *(const float2*)(r1p + 2 * qq + 8);
                qa[mf][ks][0] = packh2(x0.x, x0.y);
                qa[mf][ks][1] = packh2(x1.x, x1.y);
                qa[mf][ks][2] = packh2(x2.x, x2.y);
                qa[mf][ks][3] = packh2(x3.x, x3.y);
            }
    }
    __syncthreads();

    // V d-positions (kperm16) for AV A-frags
    int pdl[2], pdh[2];
#pragma unroll
    for (int mf = 0; mf < 2; ++mf) {
        pdl[mf] = kperm16(mf * 16 + g);
        pdh[mf] = kperm16(mf * 16 + g + 8);
    }

    float dT[2][4][4];
#pragma unroll
    for (int mf = 0; mf < 2; ++mf)
#pragma unroll
        for (int nf = 0; nf < 4; ++nf)
#pragma unroll
            for (int r = 0; r < 4; ++r) dT[mf][nf][r] = 0.f;
    float norm[4] = {0.f, 0.f, 0.f, 0.f};

#pragma unroll 1
    for (int ch = 0; ch < 9; ++ch) {
        const int t0 = ch * 16;

        // ---- QK: 2 n-blocks of 8 keys ----
        float c[2][2][4];
#pragma unroll
        for (int nt = 0; nt < 2; ++nt) {
            const int ek = tbl[min(t0 + nt * 8 + g, 139)];
            const int srow = (ek & 255) * AHJ + ((ek >> 8) & 255) + wcol0;
            const __half* kr = Ks + srow * RSA;
            const uint2 b0 = *(const uint2*)(kr + 4 * qq);
            const uint2 b1 = *(const uint2*)(kr + 16 + 4 * qq);
#pragma unroll
            for (int mf = 0; mf < 2; ++mf) {
                c[mf][nt][0] = c[mf][nt][1] = c[mf][nt][2] = c[mf][nt][3] = 0.f;
                mma_f16(c[mf][nt], qa[mf][0], (const uint32_t*)&b0);
                mma_f16(c[mf][nt], qa[mf][1], (const uint32_t*)&b1);
            }
        }

        // ---- mask + exp ----
        float ev[4][2][2];
        int rrow[2][2];
#pragma unroll
        for (int nt = 0; nt < 2; ++nt)
#pragma unroll
            for (int cc = 0; cc < 2; ++cc) {
                const int t = t0 + nt * 8 + 2 * qq + cc;
                const int e = tbl[min(t, 139)];
                const int ry = e & 255, rx = (e >> 8) & 255, r13 = e >> 16;
                rrow[nt][cc] = ry * AHJ + rx + wcol0;
                const bool tv = t < 140;
#pragma unroll
                for (int s = 0; s < 4; ++s) {
                    const float cv = c[s >> 1][nt][(s & 1) * 2 + cc];
                    const bool v = tv && ((unsigned)(ry - ryq[s]) <= 6u)
                                      && ((unsigned)(rx - rxq[s]) <= 6u);
                    int bi = r13 + CBr[s];
                    bi = max(min(bi, 168), 0);
                    const float e1 = v ? __expf(cv + rpbs[bi]) : 0.f;
                    ev[s][nt][cc] = e1;
                    norm[s] += e1;
                }
            }

        // ---- P -> AV B-frags (no shuffle: same-lane identity) ----
        uint32_t pb[4][2];
#pragma unroll
        for (int nf = 0; nf < 4; ++nf) {
            pb[nf][0] = packh2(ev[nf][0][0], ev[nf][0][1]);
            pb[nf][1] = packh2(ev[nf][1][0], ev[nf][1][1]);
        }

        // ---- AV: A-frags from V (fp16 scalar loads) ----
        const int r00 = rrow[0][0], r01 = rrow[0][1];
        const int r10 = rrow[1][0], r11 = rrow[1][1];
        uint32_t av[2][4];
#pragma unroll
        for (int mf = 0; mf < 2; ++mf) {
            const int dl = pdl[mf], dh = pdh[mf];
            av[mf][0] = packhh(Vs[r00 * RSA + dl], Vs[r01 * RSA + dl]);
            av[mf][1] = packhh(Vs[r00 * RSA + dh], Vs[r01 * RSA + dh]);
            av[mf][2] = packhh(Vs[r10 * RSA + dl], Vs[r11 * RSA + dl]);
            av[mf][3] = packhh(Vs[r10 * RSA + dh], Vs[r11 * RSA + dh]);
        }
#pragma unroll
        for (int nf = 0; nf < 4; ++nf) {
            mma_f16(dT[0][nf], av[0], pb[nf]);
            mma_f16(dT[1][nf], av[1], pb[nf]);
        }
    }

    // ---- normalize + store ----
#pragma unroll
    for (int s = 0; s < 4; ++s) {
        float n = norm[s];
        n += __shfl_xor_sync(FULL, n, 1);
        n += __shfl_xor_sync(FULL, n, 2);
        if (qq == 0)
            normsm[warp * 32 + (s >> 1) * 16 + (s & 1) * 8 + g] = 1.f / n;
    }
    __syncwarp();

#pragma unroll
    for (int mf = 0; mf < 2; ++mf) {
        const int d0 = mf * 16 + g, d1 = d0 + 8;
        const int kp0 = kperm16(d0), kp1 = kperm16(d1);
#pragma unroll
        for (int nf = 0; nf < 4; ++nf) {
            const int q0 = nf * 8 + 2 * qq, q1 = q0 + 1;
            const float iv0 = normsm[warp * 32 + q0];
            const float iv1 = normsm[warp * 32 + q1];
            __half* p0 = g_ao + ((size_t)b * HW + (i0 + (q0 >> 2)) * WID + j0 + oxw + (q0 & 3)) * CH + head * HD;
            __half* p1 = g_ao + ((size_t)b * HW + (i0 + (q1 >> 2)) * WID + j0 + oxw + (q1 & 3)) * CH + head * HD;
            p0[kp0] = __float2half_rn(dT[mf][nf][0] * iv0);
            p1[kp0] = __float2half_rn(dT[mf][nf][1] * iv1);
            p0[kp1] = __float2half_rn(dT[mf][nf][2] * iv0);
            p1[kp1] = __float2half_rn(dT[mf][nf][3] * iv1);
        }
    }
}

// =====================================================================
extern "C" void kernel_launch(void* const* d_in, const int* in_sizes, int n_in,
                              void* d_out, int out_size) {
    const float* x      = (const float*)d_in[0];
    const float* qkv_w  = (const float*)d_in[1];
    const float* rpb    = (const float*)d_in[2];
    const float* proj_w = (const float*)d_in[3];
    const float* proj_b = (const float*)d_in[4];
    float* out = (float*)d_out;

    cudaFuncSetAttribute(qkv_mma,  cudaFuncAttributeMaxDynamicSharedMemorySize, GEMM_SMEM_BYTES);
    cudaFuncSetAttribute(proj_mma, cudaFuncAttributeMaxDynamicSharedMemorySize, GEMM_SMEM_BYTES);
    cudaFuncSetAttribute(na_attn,  cudaFuncAttributeMaxDynamicSharedMemorySize, ATTN_SMEM);

    __half* wq_d; cudaGetSymbolAddress((void**)&wq_d, g_wq);
    __half* wp_d; cudaGetSymbolAddress((void**)&wp_d, g_wp);

    prep_w<<<(1536 * 512 + 255) / 256, 256>>>(qkv_w, wq_d, 1536 * 512);
    prep_w<<<(512 * 512 + 255) / 256, 256>>>(proj_w, wp_d, 512 * 512);
    xpose<<<dim3(HW / 32, CH / 32, BATCH), 256>>>(x);
    qkv_mma<<<dim3(1536 / 256, TOK / 128), 512, GEMM_SMEM_BYTES>>>(wq_d);
    na_attn<<<dim3(28, NH, BATCH), 128, ATTN_SMEM>>>(rpb);
    proj_mma<<<dim3(CH / 256, TOK / 128), 512, GEMM_SMEM_BYTES>>>(wp_d, proj_b, out);
}

// round 17
// speedup vs baseline: 5.8534x; 1.1495x over previous
#include <cuda_runtime.h>
#include <cuda_fp16.h>
#include <cstdint>
#include <math.h>

#define BATCH 8
#define CH    512
#define HGT   56
#define WID   56
#define HW    3136
#define NH    16
#define HD    32
#define TOK   25088
#define NKEY  49

__device__ __half g_q [(long)BATCH * NH * HW * HD];   // fp16, kperm16 along d
__device__ __half g_k [(long)BATCH * NH * HW * HD];
__device__ __half g_v [(long)BATCH * NH * HW * HD];
__device__ __half g_ao[(long)TOK * CH];               // attention out, fp16, kperm16
__device__ __half g_xt[(long)TOK * CH];               // x token-major, fp16, kperm16
__device__ __half g_wq[(long)1536 * CH];
__device__ __half g_wp[(long)CH * CH];

// fp16 m16n8k16 k-permutation: lane q reads halves {2q,2q+1,2q+8,2q+9} contiguously
__device__ __forceinline__ int kperm16(int k) {
    const int p = (k >> 1) & 7;
    return (k & ~15) | ((p & 3) << 2) | ((p >> 2) << 1) | (k & 1);
}

__device__ __forceinline__ uint32_t smem_u32(const void* p) {
    uint32_t a;
    asm("{ .reg .u64 t; cvta.to.shared.u64 t, %1; cvt.u32.u64 %0, t; }" : "=r"(a) : "l"(p));
    return a;
}
__device__ __forceinline__ void cpasync16(uint32_t dst, const void* src) {
    asm volatile("cp.async.cg.shared.global [%0], [%1], 16;" :: "r"(dst), "l"(src));
}
#define CP_COMMIT() asm volatile("cp.async.commit_group;" ::: "memory")
__device__ __forceinline__ uint32_t packh2(float lo, float hi) {
    const __half2 h = __floats2half2_rn(lo, hi);
    return *(const uint32_t*)&h;
}
__device__ __forceinline__ uint32_t packhh(__half lo, __half hi) {
    const __half2 h = __halves2half2(lo, hi);
    return *(const uint32_t*)&h;
}

__device__ __forceinline__ void mma_f16(float* c, const uint32_t* a, const uint32_t* b) {
    asm volatile(
        "mma.sync.aligned.m16n8k16.row.col.f32.f16.f16.f32 "
        "{%0,%1,%2,%3}, {%4,%5,%6,%7}, {%8,%9}, {%0,%1,%2,%3};"
        : "+f"(c[0]), "+f"(c[1]), "+f"(c[2]), "+f"(c[3])
        : "r"(a[0]), "r"(a[1]), "r"(a[2]), "r"(a[3]), "r"(b[0]), "r"(b[1]));
}

// =====================================================================
__global__ __launch_bounds__(256) void prep_w(const float* __restrict__ src,
                                              __half* __restrict__ dst, int total) {
    const int i = blockIdx.x * 256 + threadIdx.x;
    if (i < total) {
        const int k = i & 511;
        const int n = i >> 9;
        dst[(n << 9) | kperm16(k)] = __float2half_rn(src[i]);
    }
}

// transpose x (B,C,HW) -> x_t (TOK,CH) fp16 kperm16, half2-coalesced stores
__global__ __launch_bounds__(256) void xpose(const float* __restrict__ x) {
    __shared__ float t[32][33];
    const int b  = blockIdx.z;
    const int p0 = blockIdx.x * 32;
    const int c0 = blockIdx.y * 32;
    const int tx = threadIdx.x & 31;
    const int ty = threadIdx.x >> 5;
    const float* src = x + ((size_t)b * CH + c0) * HW + p0;
#pragma unroll
    for (int k = 0; k < 4; ++k) t[ty + 8 * k][tx] = src[(size_t)(ty + 8 * k) * HW + tx];
    __syncthreads();
    __half* dst = g_xt + ((size_t)b * HW + p0) * CH + c0;
#pragma unroll
    for (int w = 0; w < 2; ++w) {
        const int idx = threadIdx.x + w * 256;
        const int cp = idx & 15;         // c-pair index (c = 2cp, 2cp+1)
        const int pl = idx >> 4;         // 0..31 local pixel
        const int t7 = cp & 7;
        const int pp = ((cp & 8) << 1) + 4 * (t7 & 3) + 2 * (t7 >> 2);
        const __half2 h = __floats2half2_rn(t[2 * cp][pl], t[2 * cp + 1][pl]);
        *(__half2*)&dst[(size_t)pl * CH + pp] = h;
    }
}

// =====================================================================
// fp16 GEMM (unchanged, known-good): CTA 128m x 256n, KT=32, 3-stage ring
// =====================================================================
#define KT 32
#define RSH 48
#define A_BYT16 (128 * RSH * 2)
#define B_BYT16 (256 * RSH * 2)
#define STG_BYTES (A_BYT16 + B_BYT16)
#define GEMM_SMEM_BYTES (3 * STG_BYTES)

__device__ __forceinline__ void g_compute(const char* smc, float acc[2][8][4],
                                          int lane, int wm, int wn) {
    const char* Asb = smc;
    const char* Bsb = smc + A_BYT16;
    const int mrow = lane >> 2;
    const int qb = (lane & 3) * 8;
#pragma unroll
    for (int ks = 0; ks < 2; ++ks) {
        const int cob = ks * 32 + qb;
        uint32_t a[2][4];
#pragma unroll
        for (int mt = 0; mt < 2; ++mt) {
            const int m = wm + mt * 16 + mrow;
            const uint2 lo = *(const uint2*)(Asb + m * (RSH * 2) + cob);
            const uint2 hi = *(const uint2*)(Asb + (m + 8) * (RSH * 2) + cob);
            a[mt][0] = lo.x; a[mt][1] = hi.x; a[mt][2] = lo.y; a[mt][3] = hi.y;
        }
        uint32_t b[8][2];
#pragma unroll
        for (int nt = 0; nt < 8; ++nt) {
            const uint2 bv = *(const uint2*)(Bsb + (wn + nt * 8 + mrow) * (RSH * 2) + cob);
            b[nt][0] = bv.x; b[nt][1] = bv.y;
        }
#pragma unroll
        for (int mt = 0; mt < 2; ++mt)
#pragma unroll
            for (int nt = 0; nt < 8; ++nt) mma_f16(acc[mt][nt], a[mt], b[nt]);
    }
}

__device__ __forceinline__ void g_mainloop(char* dynsm, float acc[2][8][4],
                                           const __half* __restrict__ Ap,
                                           const __half* __restrict__ Bp,
                                           int m0, int n0) {
    const int tid  = threadIdx.x;
    const int lane = tid & 31, wid = tid >> 5;
    const int wm = (wid & 3) * 32, wn = (wid >> 2) * 64;
#pragma unroll
    for (int mt = 0; mt < 2; ++mt)
#pragma unroll
        for (int nt = 0; nt < 8; ++nt)
#pragma unroll
            for (int r = 0; r < 4; ++r) acc[mt][nt][r] = 0.f;

    const int r0  = tid >> 2;
    const int ch8 = (tid & 3) * 8;
    const uint32_t offA  = (uint32_t)(r0 * (RSH * 2) + (tid & 3) * 16);
    const uint32_t offB0 = offA + A_BYT16;
    const uint32_t offB1 = (uint32_t)((r0 + 128) * (RSH * 2) + (tid & 3) * 16) + A_BYT16;
    const __half* gA  = Ap + (size_t)(m0 + r0) * CH + ch8;
    const __half* gB0 = Bp + (size_t)(n0 + r0) * CH + ch8;
    const __half* gB1 = Bp + (size_t)(n0 + r0 + 128) * CH + ch8;

    const uint32_t sb0 = smem_u32(dynsm);
    const uint32_t sb1 = sb0 + STG_BYTES;
    const uint32_t sb2 = sb0 + 2 * STG_BYTES;

#define G_LOAD(base, k0) do { \
        cpasync16((base) + offA,  gA  + (k0)); \
        cpasync16((base) + offB0, gB0 + (k0)); \
        cpasync16((base) + offB1, gB1 + (k0)); \
        CP_COMMIT(); } while (0)

    G_LOAD(sb0, 0);
    G_LOAD(sb1, KT);

    const int NT = CH / KT;
    uint32_t cur = sb0, nxt = sb1, fut = sb2;

#pragma unroll 3
    for (int t = 0; t < NT; ++t) {
        if (t < NT - 1) asm volatile("cp.async.wait_group 1;" ::: "memory");
        else            asm volatile("cp.async.wait_group 0;" ::: "memory");
        __syncthreads();
        if (t + 2 < NT) G_LOAD(fut, (t + 2) * KT);
        g_compute(dynsm + (cur - sb0), acc, lane, wm, wn);
        const uint32_t tmp = cur; cur = nxt; nxt = fut; fut = tmp;
    }
#undef G_LOAD
}

__global__ __launch_bounds__(512) void qkv_mma(const __half* __restrict__ w) {
    extern __shared__ char dynsm[];
    float acc[2][8][4];
    const int n0 = blockIdx.x * 256;
    const int m0 = blockIdx.y * 128;
    g_mainloop(dynsm, acc, g_xt, w, m0, n0);

    const int lane = threadIdx.x & 31, wid = threadIdx.x >> 5;
    const int wm = (wid & 3) * 32, wn = (wid >> 2) * 64;
    const int which = n0 >> 9;
    __half* outp = (which == 0) ? g_q : (which == 1) ? g_k : g_v;
    const float sc = (which == 0) ? 0.17677669529663687f : 1.0f;

#pragma unroll
    for (int mt = 0; mt < 2; ++mt) {
        const int mA = m0 + wm + mt * 16 + (lane >> 2);
        const int bA = mA / HW, pA = mA - bA * HW;
        const int mB = mA + 8;
        const int bB = mB / HW, pB = mB - bB * HW;
#pragma unroll
        for (int nt = 0; nt < 8; ++nt) {
            const int n  = n0 + wn + nt * 8 + 2 * (lane & 3);
            const int nl = n & 511;
            const int head = nl >> 5, d = nl & 31;
            const int pp = kperm16(d);
            const __half2 h0 = __floats2half2_rn(acc[mt][nt][0] * sc, acc[mt][nt][1] * sc);
            const __half2 h1 = __floats2half2_rn(acc[mt][nt][2] * sc, acc[mt][nt][3] * sc);
            *(__half2*)&outp[((size_t)(bA * NH + head) * HW + pA) * HD + pp] = h0;
            *(__half2*)&outp[((size_t)(bB * NH + head) * HW + pB) * HD + pp] = h1;
        }
    }
}

__global__ __launch_bounds__(512) void proj_mma(const __half* __restrict__ w,
                                                const float* __restrict__ bias,
                                                float* __restrict__ out) {
    extern __shared__ char dynsm[];
    float acc[2][8][4];
    const int n0 = blockIdx.x * 256;
    const int m0 = blockIdx.y * 128;
    g_mainloop(dynsm, acc, g_ao, w, m0, n0);

    const int lane = threadIdx.x & 31, wid = threadIdx.x >> 5;
    const int wm = (wid & 3) * 32, wn = (wid >> 2) * 64;

#pragma unroll
    for (int mt = 0; mt < 2; ++mt) {
        const int mA = m0 + wm + mt * 16 + (lane >> 2);
        const int bA = mA / HW, pA = mA - bA * HW;
        const int mB = mA + 8;
        const int bB = mB / HW, pB = mB - bB * HW;
#pragma unroll
        for (int nt = 0; nt < 8; ++nt) {
            const int n = n0 + wn + nt * 8 + 2 * (lane & 3);
            const float b0 = __ldg(&bias[n]), b1 = __ldg(&bias[n + 1]);
            out[((size_t)bA * CH + n) * HW + pA]     = acc[mt][nt][0] + b0;
            out[((size_t)bA * CH + n + 1) * HW + pA] = acc[mt][nt][1] + b1;
            out[((size_t)bB * CH + n) * HW + pB]     = acc[mt][nt][2] + b0;
            out[((size_t)bB * CH + n + 1) * HW + pB] = acc[mt][nt][3] + b1;
        }
    }
}

// =====================================================================
// fp16 MMA neighborhood attention. q/k/v now fp16+kperm16 in gmem:
// K/V staging = verbatim cp.async; Q A-frags = direct LDG.64.
// =====================================================================
#define AHI 14
#define AHJ 22
#define AROWS (AHI * AHJ)   // 308
#define RSA 40              // halves per K/V smem row (80B, 16B-mult)
#define ATTN_SMEM (2 * AROWS * RSA * 2 + (176 + 128 + 144) * 4)

__global__ __launch_bounds__(128) void na_attn(const float* __restrict__ rpb) {
    extern __shared__ char asmc[];
    __half* Ks    = (__half*)asmc;
    __half* Vs    = Ks + AROWS * RSA;
    float* rpbs   = (float*)(Vs + AROWS * RSA);   // 176
    float* normsm = rpbs + 176;                   // 128
    int*   tbl    = (int*)(normsm + 128);         // 144

    const unsigned FULL = 0xffffffffu;
    const int tid = threadIdx.x, lane = tid & 31, warp = tid >> 5;
    const int qq = lane & 3, g = lane >> 2;
    const int tile = blockIdx.x, head = blockIdx.y, b = blockIdx.z;
    const int ti = tile >> 2, jt = tile & 3;
    const int i0 = ti * 8;
    const int j0 = (jt < 3) ? jt * 16 : 40;
    const int base_i = max(i0 - 3, 0);
    const int base_j = max(j0 - 3, 0);
    const int bh = b * NH + head;

    // ---- halo staging: verbatim cp.async of fp16 kperm16 rows ----
    const __half* kgh = g_k + (size_t)bh * HW * HD;
    const __half* vgh = g_v + (size_t)bh * HW * HD;
    const uint32_t ksb = smem_u32(Ks);
    const uint32_t vsb = smem_u32(Vs);
    for (int idx = tid; idx < AROWS * 4; idx += 128) {
        const int row = idx >> 2, c = idx & 3;
        const int ry = row / AHJ, rx = row - ry * AHJ;
        const int gi = min(base_i + ry, HGT - 1);
        const int gj = min(base_j + rx, WID - 1);
        const size_t go = (size_t)(gi * WID + gj) * HD + c * 8;
        const uint32_t so = (uint32_t)(row * (RSA * 2) + c * 16);
        cpasync16(ksb + so, kgh + go);
        cpasync16(vsb + so, vgh + go);
    }
    CP_COMMIT();
    for (int idx = tid; idx < 169; idx += 128) rpbs[idx] = rpb[head * 169 + idx];
    for (int t = tid; t < 144; t += 128) {
        const int ry = t / 10, rx = t - ry * 10;
        tbl[t] = ry | (rx << 8) | ((ry * 13 + rx) << 16);
    }

    const int oxw = warp * 4;
    const int minsj = min(max(j0 + oxw - 3, 0), WID - 7);
    const int wcol0 = minsj - base_j;

    int ryq[4], rxq[4], CBr[4];
#pragma unroll
    for (int s = 0; s < 4; ++s) {
        const int m = (s >> 1) * 16 + (s & 1) * 8 + g;
        const int qy = m >> 2, qxl = m & 3;
        const int i = i0 + qy, j = j0 + oxw + qxl;
        const int si = min(max(i - 3, 0), HGT - 7);
        const int sj = min(max(j - 3, 0), WID - 7);
        ryq[s] = si - base_i;
        rxq[s] = sj - minsj;
        CBr[s] = (base_i - i + 6) * 13 + (minsj - j + 6);
    }

    // ---- Q A-frags: direct LDG.64 from fp16 kperm16 q ----
    uint32_t qa[2][2][4];
    {
        const __half* qbase = g_q + (size_t)bh * HW * HD;
        const __half* qrow[4];
#pragma unroll
        for (int h = 0; h < 4; ++h) {
            const int m = (h >> 1) * 16 + (h & 1) * 8 + g;
            qrow[h] = qbase + (size_t)((i0 + (m >> 2)) * WID + j0 + oxw + (m & 3)) * HD;
        }
#pragma unroll
        for (int mf = 0; mf < 2; ++mf)
#pragma unroll
            for (int ks = 0; ks < 2; ++ks) {
                const uint2 u0 = *(const uint2*)(qrow[mf * 2]     + ks * 16 + 4 * qq);
                const uint2 u1 = *(const uint2*)(qrow[mf * 2 + 1] + ks * 16 + 4 * qq);
                qa[mf][ks][0] = u0.x;
                qa[mf][ks][1] = u1.x;
                qa[mf][ks][2] = u0.y;
                qa[mf][ks][3] = u1.y;
            }
    }
    asm volatile("cp.async.wait_group 0;" ::: "memory");
    __syncthreads();

    // V d-positions (kperm16) for AV A-frags
    int pdl[2], pdh[2];
#pragma unroll
    for (int mf = 0; mf < 2; ++mf) {
        pdl[mf] = kperm16(mf * 16 + g);
        pdh[mf] = kperm16(mf * 16 + g + 8);
    }

    float dT[2][4][4];
#pragma unroll
    for (int mf = 0; mf < 2; ++mf)
#pragma unroll
        for (int nf = 0; nf < 4; ++nf)
#pragma unroll
            for (int r = 0; r < 4; ++r) dT[mf][nf][r] = 0.f;
    float norm[4] = {0.f, 0.f, 0.f, 0.f};

#pragma unroll 1
    for (int ch = 0; ch < 9; ++ch) {
        const int t0 = ch * 16;

        // ---- QK: 2 n-blocks of 8 keys ----
        float c[2][2][4];
#pragma unroll
        for (int nt = 0; nt < 2; ++nt) {
            const int ek = tbl[min(t0 + nt * 8 + g, 139)];
            const int srow = (ek & 255) * AHJ + ((ek >> 8) & 255) + wcol0;
            const __half* kr = Ks + srow * RSA;
            const uint2 b0 = *(const uint2*)(kr + 4 * qq);
            const uint2 b1 = *(const uint2*)(kr + 16 + 4 * qq);
#pragma unroll
            for (int mf = 0; mf < 2; ++mf) {
                c[mf][nt][0] = c[mf][nt][1] = c[mf][nt][2] = c[mf][nt][3] = 0.f;
                mma_f16(c[mf][nt], qa[mf][0], (const uint32_t*)&b0);
                mma_f16(c[mf][nt], qa[mf][1], (const uint32_t*)&b1);
            }
        }

        // ---- mask + exp ----
        float ev[4][2][2];
        int rrow[2][2];
#pragma unroll
        for (int nt = 0; nt < 2; ++nt)
#pragma unroll
            for (int cc = 0; cc < 2; ++cc) {
                const int t = t0 + nt * 8 + 2 * qq + cc;
                const int e = tbl[min(t, 139)];
                const int ry = e & 255, rx = (e >> 8) & 255, r13 = e >> 16;
                rrow[nt][cc] = ry * AHJ + rx + wcol0;
                const bool tv = t < 140;
#pragma unroll
                for (int s = 0; s < 4; ++s) {
                    const float cv = c[s >> 1][nt][(s & 1) * 2 + cc];
                    const bool v = tv && ((unsigned)(ry - ryq[s]) <= 6u)
                                      && ((unsigned)(rx - rxq[s]) <= 6u);
                    int bi = r13 + CBr[s];
                    bi = max(min(bi, 168), 0);
                    const float e1 = v ? __expf(cv + rpbs[bi]) : 0.f;
                    ev[s][nt][cc] = e1;
                    norm[s] += e1;
                }
            }

        // ---- P -> AV B-frags (no shuffle: same-lane identity) ----
        uint32_t pb[4][2];
#pragma unroll
        for (int nf = 0; nf < 4; ++nf) {
            pb[nf][0] = packh2(ev[nf][0][0], ev[nf][0][1]);
            pb[nf][1] = packh2(ev[nf][1][0], ev[nf][1][1]);
        }

        // ---- AV: A-frags from V (fp16 scalar loads) ----
        const int r00 = rrow[0][0], r01 = rrow[0][1];
        const int r10 = rrow[1][0], r11 = rrow[1][1];
        uint32_t av[2][4];
#pragma unroll
        for (int mf = 0; mf < 2; ++mf) {
            const int dl = pdl[mf], dh = pdh[mf];
            av[mf][0] = packhh(Vs[r00 * RSA + dl], Vs[r01 * RSA + dl]);
            av[mf][1] = packhh(Vs[r00 * RSA + dh], Vs[r01 * RSA + dh]);
            av[mf][2] = packhh(Vs[r10 * RSA + dl], Vs[r11 * RSA + dl]);
            av[mf][3] = packhh(Vs[r10 * RSA + dh], Vs[r11 * RSA + dh]);
        }
#pragma unroll
        for (int nf = 0; nf < 4; ++nf) {
            mma_f16(dT[0][nf], av[0], pb[nf]);
            mma_f16(dT[1][nf], av[1], pb[nf]);
        }
    }

    // ---- normalize + store ----
#pragma unroll
    for (int s = 0; s < 4; ++s) {
        float n = norm[s];
        n += __shfl_xor_sync(FULL, n, 1);
        n += __shfl_xor_sync(FULL, n, 2);
        if (qq == 0)
            normsm[warp * 32 + (s >> 1) * 16 + (s & 1) * 8 + g] = 1.f / n;
    }
    __syncwarp();

#pragma unroll
    for (int mf = 0; mf < 2; ++mf) {
        const int d0 = mf * 16 + g, d1 = d0 + 8;
        const int kp0 = kperm16(d0), kp1 = kperm16(d1);
#pragma unroll
        for (int nf = 0; nf < 4; ++nf) {
            const int q0 = nf * 8 + 2 * qq, q1 = q0 + 1;
            const float iv0 = normsm[warp * 32 + q0];
            const float iv1 = normsm[warp * 32 + q1];
            __half* p0 = g_ao + ((size_t)b * HW + (i0 + (q0 >> 2)) * WID + j0 + oxw + (q0 & 3)) * CH + head * HD;
            __half* p1 = g_ao + ((size_t)b * HW + (i0 + (q1 >> 2)) * WID + j0 + oxw + (q1 & 3)) * CH + head * HD;
            p0[kp0] = __float2half_rn(dT[mf][nf][0] * iv0);
            p1[kp0] = __float2half_rn(dT[mf][nf][1] * iv1);
            p0[kp1] = __float2half_rn(dT[mf][nf][2] * iv0);
            p1[kp1] = __float2half_rn(dT[mf][nf][3] * iv1);
        }
    }
}

// =====================================================================
extern "C" void kernel_launch(void* const* d_in, const int* in_sizes, int n_in,
                              void* d_out, int out_size) {
    const float* x      = (const float*)d_in[0];
    const float* qkv_w  = (const float*)d_in[1];
    const float* rpb    = (const float*)d_in[2];
    const float* proj_w = (const float*)d_in[3];
    const float* proj_b = (const float*)d_in[4];
    float* out = (float*)d_out;

    cudaFuncSetAttribute(qkv_mma,  cudaFuncAttributeMaxDynamicSharedMemorySize, GEMM_SMEM_BYTES);
    cudaFuncSetAttribute(proj_mma, cudaFuncAttributeMaxDynamicSharedMemorySize, GEMM_SMEM_BYTES);
    cudaFuncSetAttribute(na_attn,  cudaFuncAttributeMaxDynamicSharedMemorySize, ATTN_SMEM);

    __half* wq_d; cudaGetSymbolAddress((void**)&wq_d, g_wq);
    __half* wp_d; cudaGetSymbolAddress((void**)&wp_d, g_wp);

    prep_w<<<(1536 * 512 + 255) / 256, 256>>>(qkv_w, wq_d, 1536 * 512);
    prep_w<<<(512 * 512 + 255) / 256, 256>>>(proj_w, wp_d, 512 * 512);
    xpose<<<dim3(HW / 32, CH / 32, BATCH), 256>>>(x);
    qkv_mma<<<dim3(1536 / 256, TOK / 128), 512, GEMM_SMEM_BYTES>>>(wq_d);
    na_attn<<<dim3(28, NH, BATCH), 128, ATTN_SMEM>>>(rpb);
    proj_mma<<<dim3(CH / 256, TOK / 128), 512, GEMM_SMEM_BYTES>>>(wp_d, proj_b, out);
}